// round 4
// baseline (speedup 1.0000x reference)
#include <cuda_runtime.h>
#include <cuda_bf16.h>
#include <cuda_fp8.h>
#include <cstdint>
#include <cstddef>

// ---------------- problem constants ----------------
#define NB 4
#define NT 4096
#define ND 1024
#define NH 16
#define NE 64
#define NBH (NB*NH)     // 64
#define NM (NB*NT)      // 16384
#define SPLITR 8
#define TCH (NT/SPLITR) // 512

// ---------------- GEMM tiling ----------------
#define BM 128
#define BN 128
// both loops use 128-byte k-rows per chunk:
//  fp8  chunk: 128 fp8 elems   (16 chunks over K8=2048)
//  bf16 chunk: 64  bf16 elems  (16 chunks over Kb=1024)
#define NCH8 16
#define NCHB 16
#define TILE_BYTES (BM*128)         // 16384
#define STAGE_BYTES (2*TILE_BYTES)  // 32768
#define STAGES 3
#define GEMM_SMEM (STAGES*STAGE_BYTES)  // 98304
#define SCL 512.0f
#define ISCL (1.0f/512.0f)

// ---------------- scratch (device globals) ----------------
__device__ unsigned short g_Abf[3][(size_t)NM*ND];   // bf16 hi: q, kv, attn
__device__ unsigned char  g_A8 [3][(size_t)NM*2048]; // fp8 [hi | lo*512]
__device__ unsigned short g_Bbf[4][(size_t)ND*ND];   // bf16 hi weights [n][k]
__device__ unsigned char  g_B8 [4][(size_t)ND*2048]; // fp8 [lo*512 | hi]
__device__ float g_feat[3][(size_t)NBH*NT*NE];       // qh2, kh2, vh in [b,h,t,e]
__device__ float g_kvpart[(size_t)NBH*SPLITR*NE*NE];
__device__ float g_kspart[(size_t)NBH*SPLITR*NE];
__device__ float g_kvsum[(size_t)NBH*NE*NE];
__device__ float g_ksum[(size_t)NBH*NE];

// ---------------- helpers ----------------
__device__ __forceinline__ uint32_t s2u(const void* p) {
    uint32_t a;
    asm("{ .reg .u64 t; cvta.to.shared.u64 t, %1; cvt.u32.u64 %0, t; }" : "=r"(a) : "l"(p));
    return a;
}
__device__ __forceinline__ uint32_t swz(uint32_t b) { return b ^ ((b >> 3) & 0x70); }

__device__ __forceinline__ void cpasync16(uint32_t dst, const void* src) {
    asm volatile("cp.async.cg.shared.global [%0], [%1], 16;" :: "r"(dst), "l"(src));
}
__device__ __forceinline__ void cp_commit() {
    asm volatile("cp.async.commit_group;" ::: "memory");
}
template<int N>
__device__ __forceinline__ void cp_wait() {
    asm volatile("cp.async.wait_group %0;" :: "n"(N) : "memory");
}
__device__ __forceinline__ void ldsm4(uint32_t* r, uint32_t addr) {
    asm volatile("ldmatrix.sync.aligned.m8n8.x4.shared.b16 {%0,%1,%2,%3}, [%4];"
                 : "=r"(r[0]), "=r"(r[1]), "=r"(r[2]), "=r"(r[3]) : "r"(addr));
}
__device__ __forceinline__ void mma_bf16(float* c, const uint32_t* a, const uint32_t* b) {
    asm volatile(
        "mma.sync.aligned.m16n8k16.row.col.f32.bf16.bf16.f32 "
        "{%0,%1,%2,%3}, {%4,%5,%6,%7}, {%8,%9}, {%0,%1,%2,%3};"
        : "+f"(c[0]), "+f"(c[1]), "+f"(c[2]), "+f"(c[3])
        : "r"(a[0]), "r"(a[1]), "r"(a[2]), "r"(a[3]), "r"(b[0]), "r"(b[1]));
}
__device__ __forceinline__ void mma_fp8(float* c, const uint32_t* a, const uint32_t* b) {
    asm volatile(
        "mma.sync.aligned.m16n8k32.row.col.f32.e4m3.e4m3.f32 "
        "{%0,%1,%2,%3}, {%4,%5,%6,%7}, {%8,%9}, {%0,%1,%2,%3};"
        : "+f"(c[0]), "+f"(c[1]), "+f"(c[2]), "+f"(c[3])
        : "r"(a[0]), "r"(a[1]), "r"(a[2]), "r"(a[3]), "r"(b[0]), "r"(b[1]));
}

__device__ __forceinline__ void split1(float v, unsigned short& h, float& lo) {
    __nv_bfloat16 bh = __float2bfloat16(v);
    h  = __bfloat16_as_ushort(bh);
    lo = v - __bfloat162float(bh);
}
__device__ __forceinline__ unsigned char f2e4m3(float v) {
    return (unsigned char)__nv_cvt_float_to_fp8(v, __NV_SATFINITE, __NV_E4M3);
}

// ---------------- split kernels ----------------
// activations: Abf[m][k]=hi ; A8[m] = [fp8(hi)(0:1024) | fp8(lo*512)(1024:2048)]
__global__ void split_act(const float4* __restrict__ x,
                          unsigned short* __restrict__ Abf,
                          unsigned char* __restrict__ A8) {
    int gi = blockIdx.x * blockDim.x + threadIdx.x;  // over NM*ND/4
    if (gi >= NM*ND/4) return;
    int m = gi >> 8;
    int kq = (gi & 255) << 2;
    float4 v = x[gi];
    ushort4 h; float l0, l1, l2, l3;
    split1(v.x, h.x, l0); split1(v.y, h.y, l1);
    split1(v.z, h.z, l2); split1(v.w, h.w, l3);
    *(ushort4*)(Abf + (size_t)m * ND + kq) = h;
    uchar4 h8 = make_uchar4(f2e4m3(v.x - l0), f2e4m3(v.y - l1), f2e4m3(v.z - l2), f2e4m3(v.w - l3));
    uchar4 l8 = make_uchar4(f2e4m3(l0 * SCL), f2e4m3(l1 * SCL), f2e4m3(l2 * SCL), f2e4m3(l3 * SCL));
    unsigned char* row8 = A8 + (size_t)m * 2048;
    *(uchar4*)(row8 + kq)        = h8;
    *(uchar4*)(row8 + 1024 + kq) = l8;
}
// proj weights W[h][k][e] -> Bbf[n][k]=hi ; B8[n] = [fp8(lo*512) | fp8(hi)]
__global__ void wprep_proj(const float* __restrict__ W,
                           unsigned short* __restrict__ Bbf,
                           unsigned char* __restrict__ B8) {
    int idx = blockIdx.x * blockDim.x + threadIdx.x;
    if (idx >= ND*ND) return;
    int n = idx >> 10, k = idx & 1023;
    float v = W[((size_t)(n >> 6) * ND + k) * NE + (n & 63)];
    unsigned short h; float lo;
    split1(v, h, lo);
    Bbf[idx] = h;
    unsigned char* row8 = B8 + (size_t)n * 2048;
    row8[k]        = f2e4m3(lo * SCL);
    row8[1024 + k] = f2e4m3(v - lo);
}
__global__ void wprep_o(const float* __restrict__ W,
                        unsigned short* __restrict__ Bbf,
                        unsigned char* __restrict__ B8) {
    int idx = blockIdx.x * blockDim.x + threadIdx.x;
    if (idx >= ND*ND) return;
    int n = idx >> 10, k = idx & 1023;
    float v = W[idx];
    unsigned short h; float lo;
    split1(v, h, lo);
    Bbf[idx] = h;
    unsigned char* row8 = B8 + (size_t)n * 2048;
    row8[k]        = f2e4m3(lo * SCL);
    row8[1024 + k] = f2e4m3(v - lo);
}

// ---------------- mixed fp8+bf16 MMA GEMM ----------------
// C[M,N] = Ahi*Bhi (bf16) + 2^-9*(A8 x B8) (fp8 corrections) + bias
// MODE 0: plain fp32 row-major C
// MODE 1: C -> feat [b,h,t,e] with square epilogue
// MODE 2: C -> feat [b,h,t,e] plain
template<int MODE>
__global__ void __launch_bounds__(256, 2) gemm_mix(
    const unsigned short* __restrict__ Abf, const unsigned char* __restrict__ A8,
    const unsigned short* __restrict__ Bbf, const unsigned char* __restrict__ B8,
    const float* __restrict__ bias, float* __restrict__ C)
{
    extern __shared__ __align__(128) char smem[];
    const uint32_t sb = s2u(smem);
    const int tid = threadIdx.x, lane = tid & 31, wid = tid >> 5;
    const int m0 = blockIdx.y * BM, n0 = blockIdx.x * BN;
    const int mw = (wid >> 2) * 64;   // warp M offset
    const int nw = (wid & 3) * 32;    // warp N offset

    const int lrow = tid >> 3;        // 0..31 base row
    const int lkc  = tid & 7;         // 16B chunk in 128B row

    float acc[4][4][4];
    #pragma unroll
    for (int i = 0; i < 4; ++i)
        #pragma unroll
        for (int j = 0; j < 4; ++j)
            #pragma unroll
            for (int r = 0; r < 4; ++r) acc[i][j][r] = 0.f;

    const int arow = mw + (lane & 15);
    const int brow = nw + (lane & 7) + ((lane >> 4) & 1) * 8;

    // ========== phase 1: fp8 corrections, K8 = 2048, chunk = 128 fp8 ==========
    #pragma unroll
    for (int s = 0; s < STAGES; ++s) {
        uint32_t sA = sb + s * STAGE_BYTES;
        uint32_t sB = sA + TILE_BYTES;
        int k0 = s * 128;
        #pragma unroll
        for (int i = 0; i < 4; ++i) {
            int row = lrow + i * 32;
            uint32_t so = swz(row * 128 + lkc * 16);
            cpasync16(sA + so, A8 + (size_t)(m0 + row) * 2048 + k0 + lkc * 16);
            cpasync16(sB + so, B8 + (size_t)(n0 + row) * 2048 + k0 + lkc * 16);
        }
        cp_commit();
    }
    for (int ch = 0; ch < NCH8; ++ch) {
        cp_wait<STAGES - 1>();
        __syncthreads();
        const int s = ch % STAGES;
        const uint32_t aBase = sb + s * STAGE_BYTES;
        const uint32_t bBase = aBase + TILE_BYTES;
        #pragma unroll
        for (int k32 = 0; k32 < 4; ++k32) {
            uint32_t a[4][4], bf[2][4];
            const int acol = k32 * 32 + (lane >> 4) * 16;
            const int bcol = k32 * 32 + ((lane >> 3) & 1) * 16;
            #pragma unroll
            for (int mi = 0; mi < 4; ++mi)
                ldsm4(a[mi], aBase + swz((arow + mi * 16) * 128 + acol));
            #pragma unroll
            for (int nj = 0; nj < 2; ++nj)
                ldsm4(bf[nj], bBase + swz((brow + nj * 16) * 128 + bcol));
            #pragma unroll
            for (int mi = 0; mi < 4; ++mi)
                #pragma unroll
                for (int n8 = 0; n8 < 4; ++n8)
                    mma_fp8(acc[mi][n8], a[mi], &bf[n8 >> 1][(n8 & 1) * 2]);
        }
        __syncthreads();
        if (ch + STAGES < NCH8) {
            int k0 = (ch + STAGES) * 128;
            #pragma unroll
            for (int i = 0; i < 4; ++i) {
                int row = lrow + i * 32;
                uint32_t so = swz(row * 128 + lkc * 16);
                cpasync16(aBase + so, A8 + (size_t)(m0 + row) * 2048 + k0 + lkc * 16);
                cpasync16(bBase + so, B8 + (size_t)(n0 + row) * 2048 + k0 + lkc * 16);
            }
        }
        cp_commit();
    }
    cp_wait<0>();
    __syncthreads();

    // scale corrections by 2^-9
    #pragma unroll
    for (int i = 0; i < 4; ++i)
        #pragma unroll
        for (int j = 0; j < 4; ++j)
            #pragma unroll
            for (int r = 0; r < 4; ++r) acc[i][j][r] *= ISCL;

    // ========== phase 2: bf16 main term, Kb = 1024, chunk = 64 bf16 ==========
    #pragma unroll
    for (int s = 0; s < STAGES; ++s) {
        uint32_t sA = sb + s * STAGE_BYTES;
        uint32_t sB = sA + TILE_BYTES;
        int k0 = s * 64;
        #pragma unroll
        for (int i = 0; i < 4; ++i) {
            int row = lrow + i * 32;
            uint32_t so = swz(row * 128 + lkc * 16);
            cpasync16(sA + so, Abf + (size_t)(m0 + row) * ND + k0 + lkc * 8);
            cpasync16(sB + so, Bbf + (size_t)(n0 + row) * ND + k0 + lkc * 8);
        }
        cp_commit();
    }
    for (int ch = 0; ch < NCHB; ++ch) {
        cp_wait<STAGES - 1>();
        __syncthreads();
        const int s = ch % STAGES;
        const uint32_t aBase = sb + s * STAGE_BYTES;
        const uint32_t bBase = aBase + TILE_BYTES;
        #pragma unroll
        for (int k16 = 0; k16 < 4; ++k16) {
            uint32_t a[4][4], bf[2][4];
            const int acol = (k16 * 16 + (lane >> 4) * 8) * 2;
            const int bcol = (k16 * 16 + ((lane >> 3) & 1) * 8) * 2;
            #pragma unroll
            for (int mi = 0; mi < 4; ++mi)
                ldsm4(a[mi], aBase + swz((arow + mi * 16) * 128 + acol));
            #pragma unroll
            for (int nj = 0; nj < 2; ++nj)
                ldsm4(bf[nj], bBase + swz((brow + nj * 16) * 128 + bcol));
            #pragma unroll
            for (int mi = 0; mi < 4; ++mi)
                #pragma unroll
                for (int n8 = 0; n8 < 4; ++n8)
                    mma_bf16(acc[mi][n8], a[mi], &bf[n8 >> 1][(n8 & 1) * 2]);
        }
        __syncthreads();
        if (ch + STAGES < NCHB) {
            int k0 = (ch + STAGES) * 64;
            #pragma unroll
            for (int i = 0; i < 4; ++i) {
                int row = lrow + i * 32;
                uint32_t so = swz(row * 128 + lkc * 16);
                cpasync16(aBase + so, Abf + (size_t)(m0 + row) * ND + k0 + lkc * 8);
                cpasync16(bBase + so, Bbf + (size_t)(n0 + row) * ND + k0 + lkc * 8);
            }
        }
        cp_commit();
    }

    // epilogue
    const int g = lane >> 2, t2 = (lane & 3) * 2;
    #pragma unroll
    for (int mi = 0; mi < 4; ++mi) {
        #pragma unroll
        for (int n8 = 0; n8 < 4; ++n8) {
            int col = n0 + nw + n8 * 8 + t2;
            float b0 = bias[col], b1 = bias[col + 1];
            int r0 = m0 + mw + mi * 16 + g;
            int r1 = r0 + 8;
            float2 v0 = make_float2(acc[mi][n8][0] + b0, acc[mi][n8][1] + b1);
            float2 v1 = make_float2(acc[mi][n8][2] + b0, acc[mi][n8][3] + b1);
            if (MODE == 1) {
                v0.x *= v0.x; v0.y *= v0.y; v1.x *= v1.x; v1.y *= v1.y;
            }
            if (MODE == 0) {
                *(float2*)(C + (size_t)r0 * ND + col) = v0;
                *(float2*)(C + (size_t)r1 * ND + col) = v1;
            } else {
                int h = col >> 6, e = col & 63;
                int b_0 = r0 >> 12, t_0 = r0 & (NT - 1);
                int b_1 = r1 >> 12, t_1 = r1 & (NT - 1);
                *(float2*)(C + ((((size_t)b_0 * NH + h) * NT + t_0) * NE + e)) = v0;
                *(float2*)(C + ((((size_t)b_1 * NH + h) * NT + t_1) * NE + e)) = v1;
            }
        }
    }
}

// ---------------- kv_sum & k_sum ----------------
__global__ __launch_bounds__(256) void kvsum_partial(
    const float* __restrict__ kh2, const float* __restrict__ vh,
    float* __restrict__ kvp, float* __restrict__ ksp)
{
    int bh = blockIdx.x;
    int sp = blockIdx.y;
    const float* kb = kh2 + ((size_t)bh*NT + (size_t)sp*TCH)*NE;
    const float* vb = vh  + ((size_t)bh*NT + (size_t)sp*TCH)*NE;
    __shared__ float sk[16][NE];
    __shared__ float sv[16][NE];
    int tid = threadIdx.x;
    int d  = tid >> 2;
    int e0 = (tid & 3) << 4;
    float acc[16];
    #pragma unroll
    for (int j = 0; j < 16; ++j) acc[j] = 0.f;
    float ksacc = 0.f;

    for (int t0 = 0; t0 < TCH; t0 += 16) {
        #pragma unroll
        for (int i = 0; i < 4; ++i) {
            int idx = tid + i*256;
            ((float*)sk)[idx] = kb[(size_t)t0*NE + idx];
            ((float*)sv)[idx] = vb[(size_t)t0*NE + idx];
        }
        __syncthreads();
        #pragma unroll
        for (int tt = 0; tt < 16; ++tt) {
            float kval = sk[tt][d];
            ksacc += kval;
            #pragma unroll
            for (int j = 0; j < 16; ++j)
                acc[j] += kval * sv[tt][e0 + j];
        }
        __syncthreads();
    }
    float* outp = kvp + ((size_t)(bh*SPLITR + sp))*NE*NE + (size_t)d*NE + e0;
    #pragma unroll
    for (int j = 0; j < 16; ++j) outp[j] = acc[j];
    if ((tid & 3) == 0) ksp[(size_t)(bh*SPLITR + sp)*NE + d] = ksacc;
}

__global__ void kvsum_reduce(const float* __restrict__ kvp, const float* __restrict__ ksp,
                             float* __restrict__ kvs, float* __restrict__ kss)
{
    int bh = blockIdx.x;
    int tid = threadIdx.x;
    for (int i = tid; i < NE*NE; i += 256) {
        float s = 0.f;
        #pragma unroll
        for (int sp = 0; sp < SPLITR; ++sp)
            s += kvp[((size_t)(bh*SPLITR + sp))*NE*NE + i];
        kvs[(size_t)bh*NE*NE + i] = s;
    }
    if (tid < NE) {
        float s = 0.f;
        #pragma unroll
        for (int sp = 0; sp < SPLITR; ++sp)
            s += ksp[(size_t)(bh*SPLITR + sp)*NE + tid];
        kss[(size_t)bh*NE + tid] = s;
    }
}

// ---------------- attn = z * (qh2 @ kv_sum) -> bf16 hi + fp8 pair -----------
__global__ __launch_bounds__(256) void attn_kernel(
    const float* __restrict__ qh2, const float* __restrict__ kvs,
    const float* __restrict__ kss,
    unsigned short* __restrict__ Abf, unsigned char* __restrict__ A8)
{
    int bh = blockIdx.y;
    int tt = blockIdx.x;
    __shared__ float skv[NE][NE];
    __shared__ float sks[NE];
    int tid = threadIdx.x;
    for (int i = tid; i < NE*NE; i += 256)
        ((float*)skv)[i] = kvs[(size_t)bh*NE*NE + i];
    if (tid < NE) sks[tid] = kss[(size_t)bh*NE + tid];
    __syncthreads();

    int tl = tid >> 1;
    int e0 = (tid & 1) * 32;
    int t  = tt*128 + tl;
    const float* qrowp = qh2 + ((size_t)bh*NT + t)*NE;
    float qrow[NE];
    #pragma unroll
    for (int i = 0; i < 16; ++i) {
        float4 v = *(const float4*)(qrowp + i*4);
        qrow[i*4+0] = v.x; qrow[i*4+1] = v.y; qrow[i*4+2] = v.z; qrow[i*4+3] = v.w;
    }
    float zden = 1e-6f;
    #pragma unroll
    for (int d = 0; d < NE; ++d) zden += qrow[d] * sks[d];
    float z = 1.0f / zden;

    float acc[32];
    #pragma unroll
    for (int j = 0; j < 32; ++j) acc[j] = 0.f;
    #pragma unroll 4
    for (int d = 0; d < NE; ++d) {
        float qv = qrow[d];
        #pragma unroll
        for (int j = 0; j < 32; ++j)
            acc[j] += qv * skv[d][e0 + j];
    }
    int b = bh >> 4, h = bh & 15;
    int m = b * NT + t;
    size_t baseb = (size_t)m * ND + h * NE + e0;
    size_t base8 = (size_t)m * 2048 + h * NE + e0;
    #pragma unroll
    for (int j = 0; j < 32; j += 2) {
        float va = acc[j] * z, vb = acc[j+1] * z;
        unsigned short h0, h1; float l0, l1;
        split1(va, h0, l0);
        split1(vb, h1, l1);
        *(ushort2*)(Abf + baseb + j) = make_ushort2(h0, h1);
        A8[base8 + j]          = f2e4m3(va - l0);
        A8[base8 + j + 1]      = f2e4m3(vb - l1);
        A8[base8 + 1024 + j]   = f2e4m3(l0 * SCL);
        A8[base8 + 1024 + j+1] = f2e4m3(l1 * SCL);
    }
}

// ---------------- launch ----------------
extern "C" void kernel_launch(void* const* d_in, const int* in_sizes, int n_in,
                              void* d_out, int out_size)
{
    const float* q  = (const float*)d_in[0];
    const float* kv = (const float*)d_in[1];
    const float* Wq = (const float*)d_in[2];
    const float* bq = (const float*)d_in[3];
    const float* Wk = (const float*)d_in[4];
    const float* bk = (const float*)d_in[5];
    const float* Wv = (const float*)d_in[6];
    const float* bv = (const float*)d_in[7];
    const float* Wo = (const float*)d_in[8];
    const float* bo = (const float*)d_in[9];
    float* out = (float*)d_out;

    unsigned short *Abf, *Bbf;
    unsigned char *A8, *B8;
    float *feat, *kvp, *ksp, *kvs, *kss;
    cudaGetSymbolAddress((void**)&Abf, g_Abf);
    cudaGetSymbolAddress((void**)&A8,  g_A8);
    cudaGetSymbolAddress((void**)&Bbf, g_Bbf);
    cudaGetSymbolAddress((void**)&B8,  g_B8);
    cudaGetSymbolAddress((void**)&feat, g_feat);
    cudaGetSymbolAddress((void**)&kvp, g_kvpart);
    cudaGetSymbolAddress((void**)&ksp, g_kspart);
    cudaGetSymbolAddress((void**)&kvs, g_kvsum);
    cudaGetSymbolAddress((void**)&kss, g_ksum);

    unsigned short* Aq_bf = Abf + 0*(size_t)NM*ND;
    unsigned short* Ak_bf = Abf + 1*(size_t)NM*ND;
    unsigned short* Aa_bf = Abf + 2*(size_t)NM*ND;
    unsigned char*  Aq_8  = A8  + 0*(size_t)NM*2048;
    unsigned char*  Ak_8  = A8  + 1*(size_t)NM*2048;
    unsigned char*  Aa_8  = A8  + 2*(size_t)NM*2048;
    unsigned short* Bq_bf = Bbf + 0*(size_t)ND*ND;
    unsigned short* Bk_bf = Bbf + 1*(size_t)ND*ND;
    unsigned short* Bv_bf = Bbf + 2*(size_t)ND*ND;
    unsigned short* Bo_bf = Bbf + 3*(size_t)ND*ND;
    unsigned char*  Bq_8  = B8  + 0*(size_t)ND*2048;
    unsigned char*  Bk_8  = B8  + 1*(size_t)ND*2048;
    unsigned char*  Bv_8  = B8  + 2*(size_t)ND*2048;
    unsigned char*  Bo_8  = B8  + 3*(size_t)ND*2048;
    float* fq = feat + 0*(size_t)NBH*NT*NE;
    float* fk = feat + 1*(size_t)NBH*NT*NE;
    float* fv = feat + 2*(size_t)NBH*NT*NE;

    cudaFuncSetAttribute((const void*)gemm_mix<0>, cudaFuncAttributeMaxDynamicSharedMemorySize, GEMM_SMEM);
    cudaFuncSetAttribute((const void*)gemm_mix<1>, cudaFuncAttributeMaxDynamicSharedMemorySize, GEMM_SMEM);
    cudaFuncSetAttribute((const void*)gemm_mix<2>, cudaFuncAttributeMaxDynamicSharedMemorySize, GEMM_SMEM);

    // 1) splits
    {
        int n4 = NM*ND/4;
        int blk = (n4 + 255) / 256;
        split_act<<<blk, 256>>>((const float4*)q,  Aq_bf, Aq_8);
        split_act<<<blk, 256>>>((const float4*)kv, Ak_bf, Ak_8);
        int blk2 = (ND*ND + 255) / 256;
        wprep_proj<<<blk2, 256>>>(Wq, Bq_bf, Bq_8);
        wprep_proj<<<blk2, 256>>>(Wk, Bk_bf, Bk_8);
        wprep_proj<<<blk2, 256>>>(Wv, Bv_bf, Bv_8);
        wprep_o<<<blk2, 256>>>(Wo, Bo_bf, Bo_8);
    }
    // 2) projection GEMMs
    {
        dim3 grid(ND / BN, NM / BM);
        gemm_mix<1><<<grid, 256, GEMM_SMEM>>>(Aq_bf, Aq_8, Bq_bf, Bq_8, bq, fq);
        gemm_mix<1><<<grid, 256, GEMM_SMEM>>>(Ak_bf, Ak_8, Bk_bf, Bk_8, bk, fk);
        gemm_mix<2><<<grid, 256, GEMM_SMEM>>>(Ak_bf, Ak_8, Bv_bf, Bv_8, bv, fv);
    }
    // 3) kv_sum / k_sum
    {
        dim3 grid(NBH, SPLITR);
        kvsum_partial<<<grid, 256>>>(fk, fv, kvp, ksp);
        kvsum_reduce<<<NBH, 256>>>(kvp, ksp, kvs, kss);
    }
    // 4) attn
    {
        dim3 grid(NT / 128, NBH);
        attn_kernel<<<grid, 256>>>(fq, kvs, kss, Aa_bf, Aa_8);
    }
    // 5) output GEMM
    {
        dim3 grid(ND / BN, NM / BM);
        gemm_mix<0><<<grid, 256, GEMM_SMEM>>>(Aa_bf, Aa_8, Bo_bf, Bo_8, bo, out);
    }
}

// round 5
// speedup vs baseline: 1.3308x; 1.3308x over previous
#include <cuda_runtime.h>
#include <cuda_bf16.h>
#include <cuda_fp16.h>
#include <cstdint>
#include <cstddef>

// ---------------- problem constants ----------------
#define NB 4
#define NT 4096
#define ND 1024
#define NH 16
#define NE 64
#define NBH (NB*NH)     // 64
#define NM (NB*NT)      // 16384
#define K3 3072         // bf16x3 packed K (Q,K projections)
#define K2 2048         // fp16x2 packed K (V projection, O GEMM)
#define SPLITR 8
#define TCH (NT/SPLITR) // 512

// ---------------- GEMM tiling ----------------
#define BM 128
#define BN 128
#define TILE_BYTES (BM*128)         // 16384
#define STAGE_BYTES (2*TILE_BYTES)  // 32768
#define STAGES 3
#define GEMM_SMEM (STAGES*STAGE_BYTES)  // 98304
#define OSCL 256.0f
#define IOSCL (1.0f/256.0f)

// ---------------- scratch (device globals) ----------------
__device__ unsigned short g_Aq3[(size_t)NM*K3];   // q:    [hi | lo | hi] bf16
__device__ unsigned short g_Ak3[(size_t)NM*K3];   // kv:   [hi | lo | hi] bf16
__device__ unsigned short g_Akv2[(size_t)NM*K2];  // kv:   [hi | lo] fp16
__device__ unsigned short g_Aa2[(size_t)NM*K2];   // attn*256: [hi | lo] fp16
__device__ unsigned short g_Bq3[(size_t)ND*K3];   // Wq: [hi | hi | lo] bf16
__device__ unsigned short g_Bk3[(size_t)ND*K3];   // Wk: [hi | hi | lo] bf16
__device__ unsigned short g_Bv2[(size_t)ND*K2];   // Wv: [w16 | w16] fp16
__device__ unsigned short g_Bo2[(size_t)ND*K2];   // Wo: [w16 | w16] fp16
__device__ float g_feat[3][(size_t)NBH*NT*NE];    // qh2, kh2, vh in [b,h,t,e]
__device__ float g_kvpart[(size_t)NBH*SPLITR*NE*NE];
__device__ float g_kspart[(size_t)NBH*SPLITR*NE];
__device__ float g_kvsum[(size_t)NBH*NE*NE];
__device__ float g_ksum[(size_t)NBH*NE];

// ---------------- helpers ----------------
__device__ __forceinline__ uint32_t s2u(const void* p) {
    uint32_t a;
    asm("{ .reg .u64 t; cvta.to.shared.u64 t, %1; cvt.u32.u64 %0, t; }" : "=r"(a) : "l"(p));
    return a;
}
__device__ __forceinline__ uint32_t swz(uint32_t b) { return b ^ ((b >> 3) & 0x70); }

__device__ __forceinline__ void cpasync16(uint32_t dst, const void* src) {
    asm volatile("cp.async.cg.shared.global [%0], [%1], 16;" :: "r"(dst), "l"(src));
}
__device__ __forceinline__ void cp_commit() {
    asm volatile("cp.async.commit_group;" ::: "memory");
}
template<int N>
__device__ __forceinline__ void cp_wait() {
    asm volatile("cp.async.wait_group %0;" :: "n"(N) : "memory");
}
__device__ __forceinline__ void ldsm4(uint32_t* r, uint32_t addr) {
    asm volatile("ldmatrix.sync.aligned.m8n8.x4.shared.b16 {%0,%1,%2,%3}, [%4];"
                 : "=r"(r[0]), "=r"(r[1]), "=r"(r[2]), "=r"(r[3]) : "r"(addr));
}
__device__ __forceinline__ void mma_bf16(float* c, const uint32_t* a, const uint32_t* b) {
    asm volatile(
        "mma.sync.aligned.m16n8k16.row.col.f32.bf16.bf16.f32 "
        "{%0,%1,%2,%3}, {%4,%5,%6,%7}, {%8,%9}, {%0,%1,%2,%3};"
        : "+f"(c[0]), "+f"(c[1]), "+f"(c[2]), "+f"(c[3])
        : "r"(a[0]), "r"(a[1]), "r"(a[2]), "r"(a[3]), "r"(b[0]), "r"(b[1]));
}
__device__ __forceinline__ void mma_fp16(float* c, const uint32_t* a, const uint32_t* b) {
    asm volatile(
        "mma.sync.aligned.m16n8k16.row.col.f32.f16.f16.f32 "
        "{%0,%1,%2,%3}, {%4,%5,%6,%7}, {%8,%9}, {%0,%1,%2,%3};"
        : "+f"(c[0]), "+f"(c[1]), "+f"(c[2]), "+f"(c[3])
        : "r"(a[0]), "r"(a[1]), "r"(a[2]), "r"(a[3]), "r"(b[0]), "r"(b[1]));
}

__device__ __forceinline__ void splitbf(float v, unsigned short& h, unsigned short& l) {
    __nv_bfloat16 bh = __float2bfloat16(v);
    float r = v - __bfloat162float(bh);
    h = __bfloat16_as_ushort(bh);
    l = __bfloat16_as_ushort(__float2bfloat16(r));
}
__device__ __forceinline__ void splith(float v, unsigned short& h, unsigned short& l) {
    __half hh = __float2half_rn(v);
    float r = v - __half2float(hh);
    h = __half_as_ushort(hh);
    l = __half_as_ushort(__float2half_rn(r));
}

// ---------------- prep kernels ----------------
// q -> bf16 trip [hi | lo | hi]
__global__ void split_q(const float4* __restrict__ x, unsigned short* __restrict__ A3) {
    int gi = blockIdx.x * blockDim.x + threadIdx.x;
    if (gi >= NM*ND/4) return;
    int m = gi >> 8;
    int kq = (gi & 255) << 2;
    float4 v = x[gi];
    ushort4 h, l;
    splitbf(v.x, h.x, l.x); splitbf(v.y, h.y, l.y);
    splitbf(v.z, h.z, l.z); splitbf(v.w, h.w, l.w);
    unsigned short* row = A3 + (size_t)m * K3;
    *(ushort4*)(row + kq)        = h;
    *(ushort4*)(row + 1024 + kq) = l;
    *(ushort4*)(row + 2048 + kq) = h;
}
// kv -> bf16 trip (for K proj) AND fp16 pair (for V proj)
__global__ void split_kv(const float4* __restrict__ x,
                         unsigned short* __restrict__ A3,
                         unsigned short* __restrict__ A2) {
    int gi = blockIdx.x * blockDim.x + threadIdx.x;
    if (gi >= NM*ND/4) return;
    int m = gi >> 8;
    int kq = (gi & 255) << 2;
    float4 v = x[gi];
    ushort4 h, l;
    splitbf(v.x, h.x, l.x); splitbf(v.y, h.y, l.y);
    splitbf(v.z, h.z, l.z); splitbf(v.w, h.w, l.w);
    unsigned short* row = A3 + (size_t)m * K3;
    *(ushort4*)(row + kq)        = h;
    *(ushort4*)(row + 1024 + kq) = l;
    *(ushort4*)(row + 2048 + kq) = h;
    ushort4 h2, l2;
    splith(v.x, h2.x, l2.x); splith(v.y, h2.y, l2.y);
    splith(v.z, h2.z, l2.z); splith(v.w, h2.w, l2.w);
    unsigned short* row2 = A2 + (size_t)m * K2;
    *(ushort4*)(row2 + kq)        = h2;
    *(ushort4*)(row2 + 1024 + kq) = l2;
}
// fused weight prep: y=0 Wq(bf trip), y=1 Wk(bf trip), y=2 Wv(fp16 dup), y=3 Wo(fp16 dup)
__global__ void wprep_all(const float* __restrict__ Wq, const float* __restrict__ Wk,
                          const float* __restrict__ Wv, const float* __restrict__ Wo,
                          unsigned short* __restrict__ Bq3, unsigned short* __restrict__ Bk3,
                          unsigned short* __restrict__ Bv2, unsigned short* __restrict__ Bo2) {
    int idx = blockIdx.x * blockDim.x + threadIdx.x;
    if (idx >= ND*ND) return;
    int which = blockIdx.y;
    int n = idx >> 10, k = idx & 1023;
    if (which <= 1) {
        const float* W = (which == 0) ? Wq : Wk;
        float v = W[((size_t)(n >> 6) * ND + k) * NE + (n & 63)];
        unsigned short h, l;
        splitbf(v, h, l);
        unsigned short* row = ((which == 0) ? Bq3 : Bk3) + (size_t)n * K3;
        row[k] = h; row[1024 + k] = h; row[2048 + k] = l;
    } else {
        float v = (which == 2) ? Wv[((size_t)(n >> 6) * ND + k) * NE + (n & 63)]
                               : Wo[(size_t)n * ND + k];
        unsigned short h = __half_as_ushort(__float2half_rn(v));
        unsigned short* row = ((which == 2) ? Bv2 : Bo2) + (size_t)n * K2;
        row[k] = h; row[1024 + k] = h;
    }
}

// ---------------- MMA GEMM: C[M,N] = A[M,KTOT] x B[N,KTOT]^T (+epilogue) ----
// MODE 0: plain + bias            MODE 1: feat [b,h,t,e], square
// MODE 2: feat [b,h,t,e], plain   MODE 3: plain, acc/256 + bias
template<int MODE, int KTOT, bool HALF>
__global__ void __launch_bounds__(256, 2) gemm_mma(
    const unsigned short* __restrict__ A, const unsigned short* __restrict__ Bm,
    const float* __restrict__ bias, float* __restrict__ C)
{
    extern __shared__ __align__(128) char smem[];
    const uint32_t sb = s2u(smem);
    const int tid = threadIdx.x, lane = tid & 31, wid = tid >> 5;
    const int m0 = blockIdx.y * BM, n0 = blockIdx.x * BN;
    const int mw = (wid >> 2) * 64;
    const int nw = (wid & 3) * 32;
    const int NCH = KTOT / 64;

    const int lrow = tid >> 3;
    const int lkc  = tid & 7;

    float acc[4][4][4];
    #pragma unroll
    for (int i = 0; i < 4; ++i)
        #pragma unroll
        for (int j = 0; j < 4; ++j)
            #pragma unroll
            for (int r = 0; r < 4; ++r) acc[i][j][r] = 0.f;

    #pragma unroll
    for (int s = 0; s < STAGES; ++s) {
        uint32_t sA = sb + s * STAGE_BYTES;
        uint32_t sB = sA + TILE_BYTES;
        int k0 = s * 64;
        #pragma unroll
        for (int i = 0; i < 4; ++i) {
            int row = lrow + i * 32;
            uint32_t so = swz(row * 128 + lkc * 16);
            cpasync16(sA + so, A  + (size_t)(m0 + row) * KTOT + k0 + lkc * 8);
            cpasync16(sB + so, Bm + (size_t)(n0 + row) * KTOT + k0 + lkc * 8);
        }
        cp_commit();
    }

    const int arow = mw + (lane & 15);
    const int brow = nw + (lane & 7) + ((lane >> 4) & 1) * 8;

    for (int ch = 0; ch < NCH; ++ch) {
        cp_wait<STAGES - 1>();
        __syncthreads();
        const int s = ch % STAGES;
        const uint32_t aBase = sb + s * STAGE_BYTES;
        const uint32_t bBase = aBase + TILE_BYTES;
        #pragma unroll
        for (int k16 = 0; k16 < 4; ++k16) {
            uint32_t a[4][4], bf[2][4];
            const int acol = (k16 * 16 + (lane >> 4) * 8) * 2;
            const int bcol = (k16 * 16 + ((lane >> 3) & 1) * 8) * 2;
            #pragma unroll
            for (int mi = 0; mi < 4; ++mi)
                ldsm4(a[mi], aBase + swz((arow + mi * 16) * 128 + acol));
            #pragma unroll
            for (int nj = 0; nj < 2; ++nj)
                ldsm4(bf[nj], bBase + swz((brow + nj * 16) * 128 + bcol));
            #pragma unroll
            for (int mi = 0; mi < 4; ++mi)
                #pragma unroll
                for (int n8 = 0; n8 < 4; ++n8) {
                    if (HALF) mma_fp16(acc[mi][n8], a[mi], &bf[n8 >> 1][(n8 & 1) * 2]);
                    else      mma_bf16(acc[mi][n8], a[mi], &bf[n8 >> 1][(n8 & 1) * 2]);
                }
        }
        __syncthreads();
        if (ch + STAGES < NCH) {
            int k0 = (ch + STAGES) * 64;
            #pragma unroll
            for (int i = 0; i < 4; ++i) {
                int row = lrow + i * 32;
                uint32_t so = swz(row * 128 + lkc * 16);
                cpasync16(aBase + so, A  + (size_t)(m0 + row) * KTOT + k0 + lkc * 8);
                cpasync16(bBase + so, Bm + (size_t)(n0 + row) * KTOT + k0 + lkc * 8);
            }
        }
        cp_commit();
    }

    // epilogue
    const int g = lane >> 2, t2 = (lane & 3) * 2;
    #pragma unroll
    for (int mi = 0; mi < 4; ++mi) {
        #pragma unroll
        for (int n8 = 0; n8 < 4; ++n8) {
            int col = n0 + nw + n8 * 8 + t2;
            float b0 = bias[col], b1 = bias[col + 1];
            int r0 = m0 + mw + mi * 16 + g;
            int r1 = r0 + 8;
            float s = (MODE == 3) ? IOSCL : 1.0f;
            float2 v0 = make_float2(acc[mi][n8][0] * s + b0, acc[mi][n8][1] * s + b1);
            float2 v1 = make_float2(acc[mi][n8][2] * s + b0, acc[mi][n8][3] * s + b1);
            if (MODE == 1) {
                v0.x *= v0.x; v0.y *= v0.y; v1.x *= v1.x; v1.y *= v1.y;
            }
            if (MODE == 0 || MODE == 3) {
                *(float2*)(C + (size_t)r0 * ND + col) = v0;
                *(float2*)(C + (size_t)r1 * ND + col) = v1;
            } else {
                int h = col >> 6, e = col & 63;
                int b_0 = r0 >> 12, t_0 = r0 & (NT - 1);
                int b_1 = r1 >> 12, t_1 = r1 & (NT - 1);
                *(float2*)(C + ((((size_t)b_0 * NH + h) * NT + t_0) * NE + e)) = v0;
                *(float2*)(C + ((((size_t)b_1 * NH + h) * NT + t_1) * NE + e)) = v1;
            }
        }
    }
}

// ---------------- kv_sum & k_sum ----------------
__global__ __launch_bounds__(256) void kvsum_partial(
    const float* __restrict__ kh2, const float* __restrict__ vh,
    float* __restrict__ kvp, float* __restrict__ ksp)
{
    int bh = blockIdx.x;
    int sp = blockIdx.y;
    const float* kb = kh2 + ((size_t)bh*NT + (size_t)sp*TCH)*NE;
    const float* vb = vh  + ((size_t)bh*NT + (size_t)sp*TCH)*NE;
    __shared__ float sk[16][NE];
    __shared__ float sv[16][NE];
    int tid = threadIdx.x;
    int d  = tid >> 2;
    int e0 = (tid & 3) << 4;
    float acc[16];
    #pragma unroll
    for (int j = 0; j < 16; ++j) acc[j] = 0.f;
    float ksacc = 0.f;

    for (int t0 = 0; t0 < TCH; t0 += 16) {
        #pragma unroll
        for (int i = 0; i < 4; ++i) {
            int idx = tid + i*256;
            ((float*)sk)[idx] = kb[(size_t)t0*NE + idx];
            ((float*)sv)[idx] = vb[(size_t)t0*NE + idx];
        }
        __syncthreads();
        #pragma unroll
        for (int tt = 0; tt < 16; ++tt) {
            float kval = sk[tt][d];
            ksacc += kval;
            #pragma unroll
            for (int j = 0; j < 16; ++j)
                acc[j] += kval * sv[tt][e0 + j];
        }
        __syncthreads();
    }
    float* outp = kvp + ((size_t)(bh*SPLITR + sp))*NE*NE + (size_t)d*NE + e0;
    #pragma unroll
    for (int j = 0; j < 16; ++j) outp[j] = acc[j];
    if ((tid & 3) == 0) ksp[(size_t)(bh*SPLITR + sp)*NE + d] = ksacc;
}

__global__ void kvsum_reduce(const float* __restrict__ kvp, const float* __restrict__ ksp,
                             float* __restrict__ kvs, float* __restrict__ kss)
{
    int bh = blockIdx.x;
    int tid = threadIdx.x;
    for (int i = tid; i < NE*NE; i += 256) {
        float s = 0.f;
        #pragma unroll
        for (int sp = 0; sp < SPLITR; ++sp)
            s += kvp[((size_t)(bh*SPLITR + sp))*NE*NE + i];
        kvs[(size_t)bh*NE*NE + i] = s;
    }
    if (tid < NE) {
        float s = 0.f;
        #pragma unroll
        for (int sp = 0; sp < SPLITR; ++sp)
            s += ksp[(size_t)(bh*SPLITR + sp)*NE + tid];
        kss[(size_t)bh*NE + tid] = s;
    }
}

// ---------------- attn = z * (qh2 @ kv_sum) -> fp16 pair of attn*256 --------
__global__ __launch_bounds__(256) void attn_kernel(
    const float* __restrict__ qh2, const float* __restrict__ kvs,
    const float* __restrict__ kss, unsigned short* __restrict__ A2)
{
    int bh = blockIdx.y;
    int tt = blockIdx.x;
    __shared__ float skv[NE][NE];
    __shared__ float sks[NE];
    int tid = threadIdx.x;
    for (int i = tid; i < NE*NE; i += 256)
        ((float*)skv)[i] = kvs[(size_t)bh*NE*NE + i];
    if (tid < NE) sks[tid] = kss[(size_t)bh*NE + tid];
    __syncthreads();

    int tl = tid >> 1;
    int e0 = (tid & 1) * 32;
    int t  = tt*128 + tl;
    const float* qrowp = qh2 + ((size_t)bh*NT + t)*NE;
    float qrow[NE];
    #pragma unroll
    for (int i = 0; i < 16; ++i) {
        float4 v = *(const float4*)(qrowp + i*4);
        qrow[i*4+0] = v.x; qrow[i*4+1] = v.y; qrow[i*4+2] = v.z; qrow[i*4+3] = v.w;
    }
    float zden = 1e-6f;
    #pragma unroll
    for (int d = 0; d < NE; ++d) zden += qrow[d] * sks[d];
    float z = OSCL / zden;   // fold the 2^8 scale into z

    float acc[32];
    #pragma unroll
    for (int j = 0; j < 32; ++j) acc[j] = 0.f;
    #pragma unroll 4
    for (int d = 0; d < NE; ++d) {
        float qv = qrow[d];
        #pragma unroll
        for (int j = 0; j < 32; ++j)
            acc[j] += qv * skv[d][e0 + j];
    }
    int b = bh >> 4, h = bh & 15;
    int m = b * NT + t;
    size_t base = (size_t)m * K2 + h * NE + e0;
    #pragma unroll
    for (int j = 0; j < 32; j += 2) {
        float va = acc[j] * z, vb = acc[j+1] * z;
        unsigned short h0, l0, h1, l1;
        splith(va, h0, l0);
        splith(vb, h1, l1);
        *(ushort2*)(A2 + base + j)        = make_ushort2(h0, h1);
        *(ushort2*)(A2 + base + 1024 + j) = make_ushort2(l0, l1);
    }
}

// ---------------- launch ----------------
extern "C" void kernel_launch(void* const* d_in, const int* in_sizes, int n_in,
                              void* d_out, int out_size)
{
    const float* q  = (const float*)d_in[0];
    const float* kv = (const float*)d_in[1];
    const float* Wq = (const float*)d_in[2];
    const float* bq = (const float*)d_in[3];
    const float* Wk = (const float*)d_in[4];
    const float* bk = (const float*)d_in[5];
    const float* Wv = (const float*)d_in[6];
    const float* bv = (const float*)d_in[7];
    const float* Wo = (const float*)d_in[8];
    const float* bo = (const float*)d_in[9];
    float* out = (float*)d_out;

    unsigned short *Aq3, *Ak3, *Akv2, *Aa2, *Bq3, *Bk3, *Bv2, *Bo2;
    float *feat, *kvp, *ksp, *kvs, *kss;
    cudaGetSymbolAddress((void**)&Aq3,  g_Aq3);
    cudaGetSymbolAddress((void**)&Ak3,  g_Ak3);
    cudaGetSymbolAddress((void**)&Akv2, g_Akv2);
    cudaGetSymbolAddress((void**)&Aa2,  g_Aa2);
    cudaGetSymbolAddress((void**)&Bq3,  g_Bq3);
    cudaGetSymbolAddress((void**)&Bk3,  g_Bk3);
    cudaGetSymbolAddress((void**)&Bv2,  g_Bv2);
    cudaGetSymbolAddress((void**)&Bo2,  g_Bo2);
    cudaGetSymbolAddress((void**)&feat, g_feat);
    cudaGetSymbolAddress((void**)&kvp,  g_kvpart);
    cudaGetSymbolAddress((void**)&ksp,  g_kspart);
    cudaGetSymbolAddress((void**)&kvs,  g_kvsum);
    cudaGetSymbolAddress((void**)&kss,  g_ksum);

    float* fq = feat + 0*(size_t)NBH*NT*NE;
    float* fk = feat + 1*(size_t)NBH*NT*NE;
    float* fv = feat + 2*(size_t)NBH*NT*NE;

    cudaFuncSetAttribute((const void*)gemm_mma<1, K3, false>, cudaFuncAttributeMaxDynamicSharedMemorySize, GEMM_SMEM);
    cudaFuncSetAttribute((const void*)gemm_mma<2, K2, true>,  cudaFuncAttributeMaxDynamicSharedMemorySize, GEMM_SMEM);
    cudaFuncSetAttribute((const void*)gemm_mma<3, K2, true>,  cudaFuncAttributeMaxDynamicSharedMemorySize, GEMM_SMEM);

    // [0][1] activation splits
    {
        int n4 = NM*ND/4;
        int blk = (n4 + 255) / 256;
        split_q<<<blk, 256>>>((const float4*)q, Aq3);
        split_kv<<<blk, 256>>>((const float4*)kv, Ak3, Akv2);
    }
    // [2] fused weight prep
    {
        int blk2 = (ND*ND + 255) / 256;
        wprep_all<<<dim3(blk2, 4), 256>>>(Wq, Wk, Wv, Wo, Bq3, Bk3, Bv2, Bo2);
    }
    // [3][4][5] projection GEMMs (profiler capture window lands here)
    {
        dim3 grid(ND / BN, NM / BM);
        gemm_mma<1, K3, false><<<grid, 256, GEMM_SMEM>>>(Aq3,  Bq3, bq, fq);
        gemm_mma<1, K3, false><<<grid, 256, GEMM_SMEM>>>(Ak3,  Bk3, bk, fk);
        gemm_mma<2, K2, true ><<<grid, 256, GEMM_SMEM>>>(Akv2, Bv2, bv, fv);
    }
    // [6][7] kv_sum / k_sum
    {
        dim3 grid(NBH, SPLITR);
        kvsum_partial<<<grid, 256>>>(fk, fv, kvp, ksp);
        kvsum_reduce<<<NBH, 256>>>(kvp, ksp, kvs, kss);
    }
    // [8] attn (emits fp16 pair, scaled by 256)
    {
        dim3 grid(NT / 128, NBH);
        attn_kernel<<<grid, 256>>>(fq, kvs, kss, Aa2);
    }
    // [9] output GEMM (acc/256 + bias)
    {
        dim3 grid(ND / BN, NM / BM);
        gemm_mma<3, K2, true><<<grid, 256, GEMM_SMEM>>>(Aa2, Bo2, bo, out);
    }
}

// round 6
// speedup vs baseline: 1.4581x; 1.0956x over previous
#include <cuda_runtime.h>
#include <cuda_bf16.h>
#include <cuda_fp16.h>
#include <cstdint>
#include <cstddef>

// ---------------- problem constants ----------------
#define NB 4
#define NT 4096
#define ND 1024
#define NH 16
#define NE 64
#define NBH (NB*NH)     // 64
#define NM (NB*NT)      // 16384
#define K3 3072         // bf16x3 packed K (Q,K projections)
#define K2 2048         // fp16x2 packed K (V projection, O GEMM)
#define SPLITR 8
#define TCH (NT/SPLITR) // 512

// ---------------- GEMM tiling ----------------
#define BM 128
#define BN 128
#define TILE_BYTES (BM*128)         // 16384
#define STAGE_BYTES (2*TILE_BYTES)  // 32768
#define STAGES 3
#define GEMM_SMEM (STAGES*STAGE_BYTES)  // 98304
#define OSCL 65536.0f
#define IOSCL (1.0f/65536.0f)

// ---------------- scratch (device globals) ----------------
__device__ unsigned short g_Aq3[(size_t)NM*K3];   // q:  [hi | lo | hi] bf16
__device__ unsigned short g_Ak3[(size_t)NM*K3];   // kv: [hi | lo | hi] bf16
__device__ unsigned short g_Akv2[(size_t)NM*K2];  // kv: [hi | lo] fp16
__device__ unsigned short g_Azq[(size_t)NM*K2];   // A'' = 2^16*z*qh2: [hi | lo] fp16
__device__ unsigned short g_Bq3[(size_t)ND*K3];   // Wq: [hi | hi | lo] bf16
__device__ unsigned short g_Bk3[(size_t)ND*K3];   // Wk: [hi | hi | lo] bf16
__device__ unsigned short g_Bv2[(size_t)ND*K2];   // Wv: [w | w] fp16
__device__ unsigned short g_B2o[(size_t)NB*ND*K2];// B'' per batch: [w | w] fp16
__device__ float g_feat[3][(size_t)NBH*NT*NE];    // qh2, kh2, vh in [b,h,t,e]
__device__ float g_kvpart[(size_t)NBH*SPLITR*NE*NE];
__device__ float g_kspart[(size_t)NBH*SPLITR*NE];
__device__ float g_kvsum[(size_t)NBH*NE*NE];
__device__ float g_ksum[(size_t)NBH*NE];

// ---------------- helpers ----------------
__device__ __forceinline__ uint32_t s2u(const void* p) {
    uint32_t a;
    asm("{ .reg .u64 t; cvta.to.shared.u64 t, %1; cvt.u32.u64 %0, t; }" : "=r"(a) : "l"(p));
    return a;
}
__device__ __forceinline__ uint32_t swz(uint32_t b) { return b ^ ((b >> 3) & 0x70); }

__device__ __forceinline__ void cpasync16(uint32_t dst, const void* src) {
    asm volatile("cp.async.cg.shared.global [%0], [%1], 16;" :: "r"(dst), "l"(src));
}
__device__ __forceinline__ void cp_commit() {
    asm volatile("cp.async.commit_group;" ::: "memory");
}
template<int N>
__device__ __forceinline__ void cp_wait() {
    asm volatile("cp.async.wait_group %0;" :: "n"(N) : "memory");
}
__device__ __forceinline__ void ldsm4(uint32_t* r, uint32_t addr) {
    asm volatile("ldmatrix.sync.aligned.m8n8.x4.shared.b16 {%0,%1,%2,%3}, [%4];"
                 : "=r"(r[0]), "=r"(r[1]), "=r"(r[2]), "=r"(r[3]) : "r"(addr));
}
__device__ __forceinline__ void mma_bf16(float* c, const uint32_t* a, const uint32_t* b) {
    asm volatile(
        "mma.sync.aligned.m16n8k16.row.col.f32.bf16.bf16.f32 "
        "{%0,%1,%2,%3}, {%4,%5,%6,%7}, {%8,%9}, {%0,%1,%2,%3};"
        : "+f"(c[0]), "+f"(c[1]), "+f"(c[2]), "+f"(c[3])
        : "r"(a[0]), "r"(a[1]), "r"(a[2]), "r"(a[3]), "r"(b[0]), "r"(b[1]));
}
__device__ __forceinline__ void mma_fp16(float* c, const uint32_t* a, const uint32_t* b) {
    asm volatile(
        "mma.sync.aligned.m16n8k16.row.col.f32.f16.f16.f32 "
        "{%0,%1,%2,%3}, {%4,%5,%6,%7}, {%8,%9}, {%0,%1,%2,%3};"
        : "+f"(c[0]), "+f"(c[1]), "+f"(c[2]), "+f"(c[3])
        : "r"(a[0]), "r"(a[1]), "r"(a[2]), "r"(a[3]), "r"(b[0]), "r"(b[1]));
}

// RN split helpers (used in weight prep — small kernels)
__device__ __forceinline__ void splitbf(float v, unsigned short& h, unsigned short& l) {
    __nv_bfloat16 bh = __float2bfloat16(v);
    float r = v - __bfloat162float(bh);
    h = __bfloat16_as_ushort(bh);
    l = __bfloat16_as_ushort(__float2bfloat16(r));
}
// fast packed helpers
__device__ __forceinline__ uint32_t packlo_bf(float a, float b) {  // ushort2(bf(a), bf(b))
    uint32_t r;
    asm("cvt.rn.bf16x2.f32 %0, %1, %2;" : "=r"(r) : "f"(b), "f"(a));
    return r;
}
__device__ __forceinline__ uint32_t pack_f16(float a, float b) {   // ushort2(h(a), h(b))
    uint32_t r;
    asm("cvt.rn.f16x2.f32 %0, %1, %2;" : "=r"(r) : "f"(b), "f"(a));
    return r;
}
__device__ __forceinline__ float truncbf(float v) {
    return __uint_as_float(__float_as_uint(v) & 0xFFFF0000u);
}

// ---------------- prep kernels ----------------
// q -> bf16 trip [hi | lo | hi] (hi = truncation, lo = exact residual rounded)
__global__ void split_q(const float4* __restrict__ x, unsigned short* __restrict__ A3) {
    int gi = blockIdx.x * blockDim.x + threadIdx.x;
    if (gi >= NM*ND/4) return;
    int m = gi >> 8;
    int kq = (gi & 255) << 2;
    float4 v = x[gi];
    uint32_t h01 = __byte_perm(__float_as_uint(v.x), __float_as_uint(v.y), 0x7632);
    uint32_t h23 = __byte_perm(__float_as_uint(v.z), __float_as_uint(v.w), 0x7632);
    uint32_t l01 = packlo_bf(v.x - truncbf(v.x), v.y - truncbf(v.y));
    uint32_t l23 = packlo_bf(v.z - truncbf(v.z), v.w - truncbf(v.w));
    unsigned short* row = A3 + (size_t)m * K3;
    *(uint2*)(row + kq)        = make_uint2(h01, h23);
    *(uint2*)(row + 1024 + kq) = make_uint2(l01, l23);
    *(uint2*)(row + 2048 + kq) = make_uint2(h01, h23);
}
// kv -> bf16 trip AND fp16 pair
__global__ void split_kv(const float4* __restrict__ x,
                         unsigned short* __restrict__ A3,
                         unsigned short* __restrict__ A2) {
    int gi = blockIdx.x * blockDim.x + threadIdx.x;
    if (gi >= NM*ND/4) return;
    int m = gi >> 8;
    int kq = (gi & 255) << 2;
    float4 v = x[gi];
    uint32_t h01 = __byte_perm(__float_as_uint(v.x), __float_as_uint(v.y), 0x7632);
    uint32_t h23 = __byte_perm(__float_as_uint(v.z), __float_as_uint(v.w), 0x7632);
    uint32_t l01 = packlo_bf(v.x - truncbf(v.x), v.y - truncbf(v.y));
    uint32_t l23 = packlo_bf(v.z - truncbf(v.z), v.w - truncbf(v.w));
    unsigned short* row = A3 + (size_t)m * K3;
    *(uint2*)(row + kq)        = make_uint2(h01, h23);
    *(uint2*)(row + 1024 + kq) = make_uint2(l01, l23);
    *(uint2*)(row + 2048 + kq) = make_uint2(h01, h23);
    // fp16 pair
    uint32_t p01 = pack_f16(v.x, v.y);
    uint32_t p23 = pack_f16(v.z, v.w);
    float2 f01 = __half22float2(*(half2*)&p01);
    float2 f23 = __half22float2(*(half2*)&p23);
    uint32_t q01 = pack_f16(v.x - f01.x, v.y - f01.y);
    uint32_t q23 = pack_f16(v.z - f23.x, v.w - f23.y);
    unsigned short* row2 = A2 + (size_t)m * K2;
    *(uint2*)(row2 + kq)        = make_uint2(p01, p23);
    *(uint2*)(row2 + 1024 + kq) = make_uint2(q01, q23);
}
// weight prep: y=0 Wq(bf trip), y=1 Wk(bf trip), y=2 Wv(fp16 dup)
__global__ void wprep_all(const float* __restrict__ Wq, const float* __restrict__ Wk,
                          const float* __restrict__ Wv,
                          unsigned short* __restrict__ Bq3, unsigned short* __restrict__ Bk3,
                          unsigned short* __restrict__ Bv2) {
    int idx = blockIdx.x * blockDim.x + threadIdx.x;
    if (idx >= ND*ND) return;
    int which = blockIdx.y;
    int n = idx >> 10, k = idx & 1023;
    const float* W = (which == 0) ? Wq : (which == 1) ? Wk : Wv;
    float v = W[((size_t)(n >> 6) * ND + k) * NE + (n & 63)];
    if (which <= 1) {
        unsigned short h, l;
        splitbf(v, h, l);
        unsigned short* row = ((which == 0) ? Bq3 : Bk3) + (size_t)n * K3;
        row[k] = h; row[1024 + k] = h; row[2048 + k] = l;
    } else {
        unsigned short h = __half_as_ushort(__float2half_rn(v));
        unsigned short* row = Bv2 + (size_t)n * K2;
        row[k] = h; row[1024 + k] = h;
    }
}

// ---------------- shared GEMM mainloop (single sync per chunk) ----------------
template<bool HALF>
__device__ __forceinline__ void gemm_mainloop(
    uint32_t sb, const unsigned short* __restrict__ A, const unsigned short* __restrict__ Bm,
    int KTOT, int m0, int n0, int tid, int lane, int wid, float acc[4][4][4])
{
    const int NCH = KTOT >> 6;
    const int lrow = tid >> 3, lkc = tid & 7;
    const int mw = (wid >> 2) * 64, nw = (wid & 3) * 32;
    const int arow = mw + (lane & 15);
    const int brow = nw + (lane & 7) + ((lane >> 4) & 1) * 8;

    // prologue: stages 0..STAGES-2
    #pragma unroll
    for (int s = 0; s < STAGES - 1; ++s) {
        uint32_t sA = sb + s * STAGE_BYTES, sB = sA + TILE_BYTES;
        int k0 = s * 64;
        #pragma unroll
        for (int i = 0; i < 4; ++i) {
            int row = lrow + i * 32;
            uint32_t so = swz(row * 128 + lkc * 16);
            cpasync16(sA + so, A  + (size_t)(m0 + row) * KTOT + k0 + lkc * 8);
            cpasync16(sB + so, Bm + (size_t)(n0 + row) * KTOT + k0 + lkc * 8);
        }
        cp_commit();
    }
    for (int ch = 0; ch < NCH; ++ch) {
        cp_wait<STAGES - 2>();
        __syncthreads();
        // refill stage consumed last iteration
        int chn = ch + STAGES - 1;
        if (chn < NCH) {
            int sl = chn % STAGES;
            uint32_t sA = sb + sl * STAGE_BYTES, sB = sA + TILE_BYTES;
            int k0 = chn * 64;
            #pragma unroll
            for (int i = 0; i < 4; ++i) {
                int row = lrow + i * 32;
                uint32_t so = swz(row * 128 + lkc * 16);
                cpasync16(sA + so, A  + (size_t)(m0 + row) * KTOT + k0 + lkc * 8);
                cpasync16(sB + so, Bm + (size_t)(n0 + row) * KTOT + k0 + lkc * 8);
            }
        }
        cp_commit();
        const int s = ch % STAGES;
        const uint32_t aBase = sb + s * STAGE_BYTES;
        const uint32_t bBase = aBase + TILE_BYTES;
        #pragma unroll
        for (int k16 = 0; k16 < 4; ++k16) {
            uint32_t a[4][4], bf[2][4];
            const int acol = (k16 * 16 + (lane >> 4) * 8) * 2;
            const int bcol = (k16 * 16 + ((lane >> 3) & 1) * 8) * 2;
            #pragma unroll
            for (int mi = 0; mi < 4; ++mi)
                ldsm4(a[mi], aBase + swz((arow + mi * 16) * 128 + acol));
            #pragma unroll
            for (int nj = 0; nj < 2; ++nj)
                ldsm4(bf[nj], bBase + swz((brow + nj * 16) * 128 + bcol));
            #pragma unroll
            for (int mi = 0; mi < 4; ++mi)
                #pragma unroll
                for (int n8 = 0; n8 < 4; ++n8) {
                    if (HALF) mma_fp16(acc[mi][n8], a[mi], &bf[n8 >> 1][(n8 & 1) * 2]);
                    else      mma_bf16(acc[mi][n8], a[mi], &bf[n8 >> 1][(n8 & 1) * 2]);
                }
        }
    }
}

// ---------------- merged projection GEMM (Q | K | V via blockIdx.z) ----------
__global__ void __launch_bounds__(256, 2) gemm_proj(
    const unsigned short* __restrict__ Aq, const unsigned short* __restrict__ Ak,
    const unsigned short* __restrict__ Av,
    const unsigned short* __restrict__ Bq, const unsigned short* __restrict__ Bk,
    const unsigned short* __restrict__ Bv,
    const float* __restrict__ bq, const float* __restrict__ bk, const float* __restrict__ bv,
    float* __restrict__ fq, float* __restrict__ fk, float* __restrict__ fv)
{
    extern __shared__ __align__(128) char smem[];
    const uint32_t sb = s2u(smem);
    const int tid = threadIdx.x, lane = tid & 31, wid = tid >> 5;
    const int m0 = blockIdx.y * BM, n0 = blockIdx.x * BN;
    const int which = blockIdx.z;

    const unsigned short *A, *Bm; const float* bias; float* C; int KTOT; bool half_, sq;
    if (which == 0)      { A = Aq; Bm = Bq; bias = bq; C = fq; KTOT = K3; half_ = false; sq = true;  }
    else if (which == 1) { A = Ak; Bm = Bk; bias = bk; C = fk; KTOT = K3; half_ = false; sq = true;  }
    else                 { A = Av; Bm = Bv; bias = bv; C = fv; KTOT = K2; half_ = true;  sq = false; }

    float acc[4][4][4];
    #pragma unroll
    for (int i = 0; i < 4; ++i)
        #pragma unroll
        for (int j = 0; j < 4; ++j)
            #pragma unroll
            for (int r = 0; r < 4; ++r) acc[i][j][r] = 0.f;

    if (half_) gemm_mainloop<true >(sb, A, Bm, KTOT, m0, n0, tid, lane, wid, acc);
    else       gemm_mainloop<false>(sb, A, Bm, KTOT, m0, n0, tid, lane, wid, acc);

    // epilogue -> feat [b,h,t,e], optional square
    const int g = lane >> 2, t2 = (lane & 3) * 2;
    const int mw = (wid >> 2) * 64, nw = (wid & 3) * 32;
    #pragma unroll
    for (int mi = 0; mi < 4; ++mi) {
        #pragma unroll
        for (int n8 = 0; n8 < 4; ++n8) {
            int col = n0 + nw + n8 * 8 + t2;
            float b0 = bias[col], b1 = bias[col + 1];
            int r0 = m0 + mw + mi * 16 + g;
            int r1 = r0 + 8;
            float2 v0 = make_float2(acc[mi][n8][0] + b0, acc[mi][n8][1] + b1);
            float2 v1 = make_float2(acc[mi][n8][2] + b0, acc[mi][n8][3] + b1);
            if (sq) { v0.x *= v0.x; v0.y *= v0.y; v1.x *= v1.x; v1.y *= v1.y; }
            int h = col >> 6, e = col & 63;
            int b_0 = r0 >> 12, t_0 = r0 & (NT - 1);
            int b_1 = r1 >> 12, t_1 = r1 & (NT - 1);
            *(float2*)(C + ((((size_t)b_0 * NH + h) * NT + t_0) * NE + e)) = v0;
            *(float2*)(C + ((((size_t)b_1 * NH + h) * NT + t_1) * NE + e)) = v1;
        }
    }
}

// ---------------- O GEMM: out = (A'' x B''_b)*2^-16 + bo ----------------
__global__ void __launch_bounds__(256, 2) gemm_o(
    const unsigned short* __restrict__ A2, const unsigned short* __restrict__ B2o,
    const float* __restrict__ bo, float* __restrict__ out)
{
    extern __shared__ __align__(128) char smem[];
    const uint32_t sb = s2u(smem);
    const int tid = threadIdx.x, lane = tid & 31, wid = tid >> 5;
    const int m0 = blockIdx.y * BM, n0 = blockIdx.x * BN;
    const unsigned short* Bm = B2o + (size_t)(m0 >> 12) * ND * K2;  // per-batch B''

    float acc[4][4][4];
    #pragma unroll
    for (int i = 0; i < 4; ++i)
        #pragma unroll
        for (int j = 0; j < 4; ++j)
            #pragma unroll
            for (int r = 0; r < 4; ++r) acc[i][j][r] = 0.f;

    gemm_mainloop<true>(sb, A2, Bm, K2, m0, n0, tid, lane, wid, acc);

    const int g = lane >> 2, t2 = (lane & 3) * 2;
    const int mw = (wid >> 2) * 64, nw = (wid & 3) * 32;
    #pragma unroll
    for (int mi = 0; mi < 4; ++mi) {
        #pragma unroll
        for (int n8 = 0; n8 < 4; ++n8) {
            int col = n0 + nw + n8 * 8 + t2;
            float b0 = bo[col], b1 = bo[col + 1];
            int r0 = m0 + mw + mi * 16 + g;
            int r1 = r0 + 8;
            float2 v0 = make_float2(acc[mi][n8][0] * IOSCL + b0, acc[mi][n8][1] * IOSCL + b1);
            float2 v1 = make_float2(acc[mi][n8][2] * IOSCL + b0, acc[mi][n8][3] * IOSCL + b1);
            *(float2*)(out + (size_t)r0 * ND + col) = v0;
            *(float2*)(out + (size_t)r1 * ND + col) = v1;
        }
    }
}

// ---------------- kv_sum & k_sum ----------------
__global__ __launch_bounds__(256) void kvsum_partial(
    const float* __restrict__ kh2, const float* __restrict__ vh,
    float* __restrict__ kvp, float* __restrict__ ksp)
{
    int bh = blockIdx.x;
    int sp = blockIdx.y;
    const float* kb = kh2 + ((size_t)bh*NT + (size_t)sp*TCH)*NE;
    const float* vb = vh  + ((size_t)bh*NT + (size_t)sp*TCH)*NE;
    __shared__ float sk[16][NE];
    __shared__ float sv[16][NE];
    int tid = threadIdx.x;
    int d  = tid >> 2;
    int e0 = (tid & 3) << 4;
    float acc[16];
    #pragma unroll
    for (int j = 0; j < 16; ++j) acc[j] = 0.f;
    float ksacc = 0.f;

    for (int t0 = 0; t0 < TCH; t0 += 16) {
        #pragma unroll
        for (int i = 0; i < 4; ++i) {
            int idx = tid + i*256;
            ((float*)sk)[idx] = kb[(size_t)t0*NE + idx];
            ((float*)sv)[idx] = vb[(size_t)t0*NE + idx];
        }
        __syncthreads();
        #pragma unroll
        for (int tt = 0; tt < 16; ++tt) {
            float kval = sk[tt][d];
            ksacc += kval;
            #pragma unroll
            for (int j = 0; j < 16; ++j)
                acc[j] += kval * sv[tt][e0 + j];
        }
        __syncthreads();
    }
    float* outp = kvp + ((size_t)(bh*SPLITR + sp))*NE*NE + (size_t)d*NE + e0;
    #pragma unroll
    for (int j = 0; j < 16; ++j) outp[j] = acc[j];
    if ((tid & 3) == 0) ksp[(size_t)(bh*SPLITR + sp)*NE + d] = ksacc;
}

__global__ void kvsum_reduce(const float* __restrict__ kvp, const float* __restrict__ ksp,
                             float* __restrict__ kvs, float* __restrict__ kss)
{
    int bh = blockIdx.x;
    int tid = threadIdx.x;
    for (int i = tid; i < NE*NE; i += 256) {
        float s = 0.f;
        #pragma unroll
        for (int sp = 0; sp < SPLITR; ++sp)
            s += kvp[((size_t)(bh*SPLITR + sp))*NE*NE + i];
        kvs[(size_t)bh*NE*NE + i] = s;
    }
    if (tid < NE) {
        float s = 0.f;
        #pragma unroll
        for (int sp = 0; sp < SPLITR; ++sp)
            s += ksp[(size_t)(bh*SPLITR + sp)*NE + tid];
        kss[(size_t)bh*NE + tid] = s;
    }
}

// ---------------- B'' build: B''_b[n][h*64+d] = sum_e kvsum[b,h][d][e]*Wo[n][h*64+e]
__global__ __launch_bounds__(256) void buildB(
    const float* __restrict__ Wo, const float* __restrict__ kvs,
    unsigned short* __restrict__ B2o)
{
    int bh = blockIdx.y;
    int b = bh >> 4, h = bh & 15;
    int n0 = blockIdx.x * 64;
    __shared__ float skv[64][64];
    __shared__ float swo[64][65];
    int tid = threadIdx.x;
    for (int i = tid; i < 4096; i += 256)
        ((float*)skv)[i] = kvs[(size_t)bh*4096 + i];
    for (int i = tid; i < 4096; i += 256) {
        int n = i >> 6, e = i & 63;
        swo[n][e] = Wo[(size_t)(n0 + n) * ND + h * 64 + e];
    }
    __syncthreads();
    int n = tid & 63;
    int d0 = (tid >> 6) * 16;
    float acc[16];
    #pragma unroll
    for (int j = 0; j < 16; ++j) acc[j] = 0.f;
    for (int e = 0; e < 64; ++e) {
        float w = swo[n][e];
        #pragma unroll
        for (int j = 0; j < 16; ++j)
            acc[j] += w * skv[d0 + j][e];
    }
    size_t base = (size_t)b * ND * K2 + (size_t)(n0 + n) * K2 + h * 64 + d0;
    uint32_t pk[8];
    #pragma unroll
    for (int j = 0; j < 8; ++j) pk[j] = pack_f16(acc[2*j], acc[2*j+1]);
    *(uint4*)(&((unsigned short*)B2o)[base])        = *(uint4*)(pk);
    *(uint4*)(&((unsigned short*)B2o)[base + 8])    = *(uint4*)(pk + 4);
    *(uint4*)(&((unsigned short*)B2o)[base + 1024])     = *(uint4*)(pk);
    *(uint4*)(&((unsigned short*)B2o)[base + 1024 + 8]) = *(uint4*)(pk + 4);
}

// ---------------- zscale: A'' = 2^16 * z * qh2 -> fp16 pair ----------------
__global__ __launch_bounds__(256) void zscale(
    const float* __restrict__ qh2, const float* __restrict__ kss,
    unsigned short* __restrict__ A2)
{
    int bh = blockIdx.y;
    int b = bh >> 4, h = bh & 15;
    __shared__ float sks[NE];
    int tid = threadIdx.x;
    if (tid < NE) sks[tid] = kss[(size_t)bh*NE + tid];
    __syncthreads();

    int t = blockIdx.x * 256 + tid;
    const float* rowp = qh2 + ((size_t)bh*NT + t)*NE;
    float q2[NE];
    #pragma unroll
    for (int i = 0; i < 16; ++i) {
        float4 v = *(const float4*)(rowp + i*4);
        q2[i*4+0] = v.x; q2[i*4+1] = v.y; q2[i*4+2] = v.z; q2[i*4+3] = v.w;
    }
    float zden = 1e-6f;
    #pragma unroll
    for (int d = 0; d < NE; ++d) zden += q2[d] * sks[d];
    float z = OSCL / zden;

    uint32_t hibuf[32], lobuf[32];
    #pragma unroll
    for (int j = 0; j < 32; ++j) {
        float a = q2[2*j] * z, c = q2[2*j+1] * z;
        uint32_t hh = pack_f16(a, c);
        float2 hf = __half22float2(*(half2*)&hh);
        hibuf[j] = hh;
        lobuf[j] = pack_f16(a - hf.x, c - hf.y);
    }
    size_t base = ((size_t)b * NT + t) * K2 + h * 64;
    unsigned short* dst = A2 + base;
    #pragma unroll
    for (int j = 0; j < 8; ++j) *(uint4*)(dst + 8*j) = *(uint4*)(hibuf + 4*j);
    dst = A2 + base + 1024;
    #pragma unroll
    for (int j = 0; j < 8; ++j) *(uint4*)(dst + 8*j) = *(uint4*)(lobuf + 4*j);
}

// ---------------- launch ----------------
extern "C" void kernel_launch(void* const* d_in, const int* in_sizes, int n_in,
                              void* d_out, int out_size)
{
    const float* q  = (const float*)d_in[0];
    const float* kv = (const float*)d_in[1];
    const float* Wq = (const float*)d_in[2];
    const float* bq = (const float*)d_in[3];
    const float* Wk = (const float*)d_in[4];
    const float* bk = (const float*)d_in[5];
    const float* Wv = (const float*)d_in[6];
    const float* bv = (const float*)d_in[7];
    const float* Wo = (const float*)d_in[8];
    const float* bo = (const float*)d_in[9];
    float* out = (float*)d_out;

    unsigned short *Aq3, *Ak3, *Akv2, *Azq, *Bq3, *Bk3, *Bv2, *B2o;
    float *feat, *kvp, *ksp, *kvs, *kss;
    cudaGetSymbolAddress((void**)&Aq3,  g_Aq3);
    cudaGetSymbolAddress((void**)&Ak3,  g_Ak3);
    cudaGetSymbolAddress((void**)&Akv2, g_Akv2);
    cudaGetSymbolAddress((void**)&Azq,  g_Azq);
    cudaGetSymbolAddress((void**)&Bq3,  g_Bq3);
    cudaGetSymbolAddress((void**)&Bk3,  g_Bk3);
    cudaGetSymbolAddress((void**)&Bv2,  g_Bv2);
    cudaGetSymbolAddress((void**)&B2o,  g_B2o);
    cudaGetSymbolAddress((void**)&feat, g_feat);
    cudaGetSymbolAddress((void**)&kvp,  g_kvpart);
    cudaGetSymbolAddress((void**)&ksp,  g_kspart);
    cudaGetSymbolAddress((void**)&kvs,  g_kvsum);
    cudaGetSymbolAddress((void**)&kss,  g_ksum);

    float* fq = feat + 0*(size_t)NBH*NT*NE;
    float* fk = feat + 1*(size_t)NBH*NT*NE;
    float* fv = feat + 2*(size_t)NBH*NT*NE;

    cudaFuncSetAttribute((const void*)gemm_proj, cudaFuncAttributeMaxDynamicSharedMemorySize, GEMM_SMEM);
    cudaFuncSetAttribute((const void*)gemm_o,    cudaFuncAttributeMaxDynamicSharedMemorySize, GEMM_SMEM);

    // [0][1] activation splits
    {
        int n4 = NM*ND/4;
        int blk = (n4 + 255) / 256;
        split_q<<<blk, 256>>>((const float4*)q, Aq3);
        split_kv<<<blk, 256>>>((const float4*)kv, Ak3, Akv2);
    }
    // [2] weight prep (Wq, Wk, Wv)
    {
        int blk2 = (ND*ND + 255) / 256;
        wprep_all<<<dim3(blk2, 3), 256>>>(Wq, Wk, Wv, Bq3, Bk3, Bv2);
    }
    // [3] merged projection GEMMs (Q | K | V)
    {
        dim3 grid(ND / BN, NM / BM, 3);
        gemm_proj<<<grid, 256, GEMM_SMEM>>>(Aq3, Ak3, Akv2, Bq3, Bk3, Bv2,
                                            bq, bk, bv, fq, fk, fv);
    }
    // [4][5] kv_sum / k_sum
    {
        dim3 grid(NBH, SPLITR);
        kvsum_partial<<<grid, 256>>>(fk, fv, kvp, ksp);
        kvsum_reduce<<<NBH, 256>>>(kvp, ksp, kvs, kss);
    }
    // [6] B'' = blockstack(kvsum_h * Wo_h^T) as fp16 dup, per batch
    {
        dim3 grid(ND / 64, NBH);
        buildB<<<grid, 256>>>(Wo, kvs, B2o);
    }
    // [7] A'' = 2^16 * z * qh2 as fp16 pair
    {
        dim3 grid(NT / 256, NBH);
        zscale<<<grid, 256>>>(fq, kss, Azq);
    }
    // [8] output GEMM
    {
        dim3 grid(ND / BN, NM / BM);
        gemm_o<<<grid, 256, GEMM_SMEM>>>(Azq, B2o, bo, out);
    }
}

// round 7
// speedup vs baseline: 1.7772x; 1.2189x over previous
#include <cuda_runtime.h>
#include <cuda_bf16.h>
#include <cuda_fp16.h>
#include <cstdint>
#include <cstddef>

// ---------------- problem constants ----------------
#define NB 4
#define NT 4096
#define ND 1024
#define NH 16
#define NE 64
#define NBH (NB*NH)     // 64
#define NM (NB*NT)      // 16384
#define K2 2048         // fp16x2 packed K (all GEMMs)
#define SPLITR 8
#define TCH (NT/SPLITR) // 512

// ---------------- GEMM tiling ----------------
#define BM 128
#define BN 128
#define TILE_BYTES (BM*128)         // 16384
#define STAGE_BYTES (2*TILE_BYTES)  // 32768
#define STAGES 3
#define GEMM_SMEM (STAGES*STAGE_BYTES)  // 98304
#define NCH (K2/64)                 // 32
#define OSCL 65536.0f
#define IOSCL (1.0f/65536.0f)

// ---------------- scratch (device globals) ----------------
__device__ unsigned short g_Aq2[(size_t)NM*K2];   // q:  [hi | lo] fp16
__device__ unsigned short g_Akv2[(size_t)NM*K2];  // kv: [hi | lo] fp16
__device__ unsigned short g_Azq[(size_t)NM*K2];   // A'' = 2^16*z*qh2: [hi | lo] fp16
__device__ unsigned short g_Bq2[(size_t)ND*K2];   // Wq: [w | w] fp16
__device__ unsigned short g_Bk2[(size_t)ND*K2];   // Wk: [w | w] fp16
__device__ unsigned short g_Bv2[(size_t)ND*K2];   // Wv: [w | w] fp16
__device__ unsigned short g_B2o[(size_t)NB*ND*K2];// B'' per batch: [w | w] fp16
__device__ float g_feat[2][(size_t)NBH*NT*NE];    // kh2, vh in [b,h,t,e]
__device__ float g_kvpart[(size_t)NBH*SPLITR*NE*NE];
__device__ float g_kspart[(size_t)NBH*SPLITR*NE];
__device__ float g_kvsum[(size_t)NBH*NE*NE];
__device__ float g_ksum[(size_t)NBH*NE];

// ---------------- helpers ----------------
__device__ __forceinline__ uint32_t s2u(const void* p) {
    uint32_t a;
    asm("{ .reg .u64 t; cvta.to.shared.u64 t, %1; cvt.u32.u64 %0, t; }" : "=r"(a) : "l"(p));
    return a;
}
__device__ __forceinline__ uint32_t swz(uint32_t b) { return b ^ ((b >> 3) & 0x70); }

__device__ __forceinline__ void cpasync16(uint32_t dst, const void* src) {
    asm volatile("cp.async.cg.shared.global [%0], [%1], 16;" :: "r"(dst), "l"(src));
}
__device__ __forceinline__ void cp_commit() {
    asm volatile("cp.async.commit_group;" ::: "memory");
}
template<int N>
__device__ __forceinline__ void cp_wait() {
    asm volatile("cp.async.wait_group %0;" :: "n"(N) : "memory");
}
__device__ __forceinline__ void ldsm4(uint32_t* r, uint32_t addr) {
    asm volatile("ldmatrix.sync.aligned.m8n8.x4.shared.b16 {%0,%1,%2,%3}, [%4];"
                 : "=r"(r[0]), "=r"(r[1]), "=r"(r[2]), "=r"(r[3]) : "r"(addr));
}
__device__ __forceinline__ void mma_fp16(float* c, const uint32_t* a, const uint32_t* b) {
    asm volatile(
        "mma.sync.aligned.m16n8k16.row.col.f32.f16.f16.f32 "
        "{%0,%1,%2,%3}, {%4,%5,%6,%7}, {%8,%9}, {%0,%1,%2,%3};"
        : "+f"(c[0]), "+f"(c[1]), "+f"(c[2]), "+f"(c[3])
        : "r"(a[0]), "r"(a[1]), "r"(a[2]), "r"(a[3]), "r"(b[0]), "r"(b[1]));
}
__device__ __forceinline__ uint32_t pack_f16(float a, float b) {   // ushort2(h(a), h(b))
    uint32_t r;
    asm("cvt.rn.f16x2.f32 %0, %1, %2;" : "=r"(r) : "f"(b), "f"(a));
    return r;
}

// ---------------- prep kernels ----------------
// x -> fp16 pair [hi | lo] ; grid.y selects (q -> Aq2) / (kv -> Akv2)
__global__ void split_pair(const float4* __restrict__ xq, const float4* __restrict__ xkv,
                           unsigned short* __restrict__ Aq2, unsigned short* __restrict__ Akv2) {
    int gi = blockIdx.x * blockDim.x + threadIdx.x;
    if (gi >= NM*ND/4) return;
    const float4* x = (blockIdx.y == 0) ? xq : xkv;
    unsigned short* A2 = (blockIdx.y == 0) ? Aq2 : Akv2;
    int m = gi >> 8;
    int kq = (gi & 255) << 2;
    float4 v = x[gi];
    uint32_t p01 = pack_f16(v.x, v.y);
    uint32_t p23 = pack_f16(v.z, v.w);
    float2 f01 = __half22float2(*(half2*)&p01);
    float2 f23 = __half22float2(*(half2*)&p23);
    uint32_t q01 = pack_f16(v.x - f01.x, v.y - f01.y);
    uint32_t q23 = pack_f16(v.z - f23.x, v.w - f23.y);
    unsigned short* row = A2 + (size_t)m * K2;
    *(uint2*)(row + kq)        = make_uint2(p01, p23);
    *(uint2*)(row + 1024 + kq) = make_uint2(q01, q23);
}
// weight prep: y in {0,1,2} -> Wq,Wk,Wv as fp16 dup [w | w], B[n][k], n=h*64+e
__global__ void wprep3(const float* __restrict__ Wq, const float* __restrict__ Wk,
                       const float* __restrict__ Wv,
                       unsigned short* __restrict__ Bq2, unsigned short* __restrict__ Bk2,
                       unsigned short* __restrict__ Bv2) {
    int idx = blockIdx.x * blockDim.x + threadIdx.x;
    if (idx >= ND*ND) return;
    int which = blockIdx.y;
    int n = idx >> 10, k = idx & 1023;
    const float* W = (which == 0) ? Wq : (which == 1) ? Wk : Wv;
    float v = W[((size_t)(n >> 6) * ND + k) * NE + (n & 63)];
    unsigned short h = __half_as_ushort(__float2half_rn(v));
    unsigned short* row = ((which == 0) ? Bq2 : (which == 1) ? Bk2 : Bv2) + (size_t)n * K2;
    row[k] = h; row[1024 + k] = h;
}

// ---------------- shared fp16 GEMM mainloop (K fixed = K2) ----------------
__device__ __forceinline__ void gemm_mainloop(
    uint32_t sb, const unsigned short* __restrict__ A, const unsigned short* __restrict__ Bm,
    int m0, int n0, int tid, int lane, int wid, float acc[4][4][4])
{
    const int lrow = tid >> 3, lkc = tid & 7;
    const int mw = (wid >> 2) * 64, nw = (wid & 3) * 32;
    const int arow = mw + (lane & 15);
    const int brow = nw + (lane & 7) + ((lane >> 4) & 1) * 8;

    #pragma unroll
    for (int s = 0; s < STAGES - 1; ++s) {
        uint32_t sA = sb + s * STAGE_BYTES, sB = sA + TILE_BYTES;
        int k0 = s * 64;
        #pragma unroll
        for (int i = 0; i < 4; ++i) {
            int row = lrow + i * 32;
            uint32_t so = swz(row * 128 + lkc * 16);
            cpasync16(sA + so, A  + (size_t)(m0 + row) * K2 + k0 + lkc * 8);
            cpasync16(sB + so, Bm + (size_t)(n0 + row) * K2 + k0 + lkc * 8);
        }
        cp_commit();
    }
    for (int ch = 0; ch < NCH; ++ch) {
        cp_wait<STAGES - 2>();
        __syncthreads();
        int chn = ch + STAGES - 1;
        if (chn < NCH) {
            int sl = chn % STAGES;
            uint32_t sA = sb + sl * STAGE_BYTES, sB = sA + TILE_BYTES;
            int k0 = chn * 64;
            #pragma unroll
            for (int i = 0; i < 4; ++i) {
                int row = lrow + i * 32;
                uint32_t so = swz(row * 128 + lkc * 16);
                cpasync16(sA + so, A  + (size_t)(m0 + row) * K2 + k0 + lkc * 8);
                cpasync16(sB + so, Bm + (size_t)(n0 + row) * K2 + k0 + lkc * 8);
            }
        }
        cp_commit();
        const int s = ch % STAGES;
        const uint32_t aBase = sb + s * STAGE_BYTES;
        const uint32_t bBase = aBase + TILE_BYTES;
        #pragma unroll
        for (int k16 = 0; k16 < 4; ++k16) {
            uint32_t a[4][4], bf[2][4];
            const int acol = (k16 * 16 + (lane >> 4) * 8) * 2;
            const int bcol = (k16 * 16 + ((lane >> 3) & 1) * 8) * 2;
            #pragma unroll
            for (int mi = 0; mi < 4; ++mi)
                ldsm4(a[mi], aBase + swz((arow + mi * 16) * 128 + acol));
            #pragma unroll
            for (int nj = 0; nj < 2; ++nj)
                ldsm4(bf[nj], bBase + swz((brow + nj * 16) * 128 + bcol));
            #pragma unroll
            for (int mi = 0; mi < 4; ++mi)
                #pragma unroll
                for (int n8 = 0; n8 < 4; ++n8)
                    mma_fp16(acc[mi][n8], a[mi], &bf[n8 >> 1][(n8 & 1) * 2]);
        }
    }
}

// ---------------- K|V projection GEMM (blockIdx.z: 0=K squared, 1=V) --------
__global__ void __launch_bounds__(256, 2) gemm_kv(
    const unsigned short* __restrict__ Akv,
    const unsigned short* __restrict__ Bk, const unsigned short* __restrict__ Bv,
    const float* __restrict__ bk, const float* __restrict__ bv,
    float* __restrict__ fk, float* __restrict__ fv)
{
    extern __shared__ __align__(128) char smem[];
    const uint32_t sb = s2u(smem);
    const int tid = threadIdx.x, lane = tid & 31, wid = tid >> 5;
    const int m0 = blockIdx.y * BM, n0 = blockIdx.x * BN;
    const int which = blockIdx.z;
    const unsigned short* Bm = (which == 0) ? Bk : Bv;
    const float* bias = (which == 0) ? bk : bv;
    float* C = (which == 0) ? fk : fv;

    float acc[4][4][4];
    #pragma unroll
    for (int i = 0; i < 4; ++i)
        #pragma unroll
        for (int j = 0; j < 4; ++j)
            #pragma unroll
            for (int r = 0; r < 4; ++r) acc[i][j][r] = 0.f;

    gemm_mainloop(sb, Akv, Bm, m0, n0, tid, lane, wid, acc);

    const int g = lane >> 2, t2 = (lane & 3) * 2;
    const int mw = (wid >> 2) * 64, nw = (wid & 3) * 32;
    #pragma unroll
    for (int mi = 0; mi < 4; ++mi) {
        #pragma unroll
        for (int n8 = 0; n8 < 4; ++n8) {
            int col = n0 + nw + n8 * 8 + t2;
            float b0 = bias[col], b1 = bias[col + 1];
            int r0 = m0 + mw + mi * 16 + g;
            int r1 = r0 + 8;
            float2 v0 = make_float2(acc[mi][n8][0] + b0, acc[mi][n8][1] + b1);
            float2 v1 = make_float2(acc[mi][n8][2] + b0, acc[mi][n8][3] + b1);
            if (which == 0) { v0.x *= v0.x; v0.y *= v0.y; v1.x *= v1.x; v1.y *= v1.y; }
            int h = col >> 6, e = col & 63;
            int b_0 = r0 >> 12, t_0 = r0 & (NT - 1);
            int b_1 = r1 >> 12, t_1 = r1 & (NT - 1);
            *(float2*)(C + ((((size_t)b_0 * NH + h) * NT + t_0) * NE + e)) = v0;
            *(float2*)(C + ((((size_t)b_1 * NH + h) * NT + t_1) * NE + e)) = v1;
        }
    }
}

// ---------------- Q projection GEMM fused with z-scale -> A'' ---------------
__global__ void __launch_bounds__(256, 2) gemm_qfused(
    const unsigned short* __restrict__ Aq, const unsigned short* __restrict__ Bq,
    const float* __restrict__ bq, const float* __restrict__ kss,
    unsigned short* __restrict__ Azq)
{
    extern __shared__ __align__(128) char smem[];
    const uint32_t sb = s2u(smem);
    const int tid = threadIdx.x, lane = tid & 31, wid = tid >> 5;
    const int m0 = blockIdx.y * BM, n0 = blockIdx.x * BN;

    float acc[4][4][4];
    #pragma unroll
    for (int i = 0; i < 4; ++i)
        #pragma unroll
        for (int j = 0; j < 4; ++j)
            #pragma unroll
            for (int r = 0; r < 4; ++r) acc[i][j][r] = 0.f;

    gemm_mainloop(sb, Aq, Bq, m0, n0, tid, lane, wid, acc);

    const int g = lane >> 2, t2 = (lane & 3) * 2;
    const int mw = (wid >> 2) * 64, nw = (wid & 3) * 32;
    const int b = m0 >> 12;
    const int hloc = nw >> 6;                 // 0 or 1
    const int h = (n0 >> 6) + hloc;           // global head 0..15
    const int bh = b * NH + h;

    // ks values for this thread's 8 columns
    float ks0[4], ks1[4];
    #pragma unroll
    for (int n8 = 0; n8 < 4; ++n8) {
        int colh = (nw & 32) + n8 * 8 + t2;
        ks0[n8] = kss[bh * NE + colh];
        ks1[n8] = kss[bh * NE + colh + 1];
    }

    float* zred = (float*)smem;               // 256 floats: [t_local][head_local]
    __syncthreads();                          // mainloop smem no longer needed
    if (tid < 256) zred[tid] = 0.f;
    __syncthreads();

    // square (+bias) into acc; accumulate z-denominator partials
    float part[4][2];
    #pragma unroll
    for (int mi = 0; mi < 4; ++mi) { part[mi][0] = 0.f; part[mi][1] = 0.f; }
    #pragma unroll
    for (int mi = 0; mi < 4; ++mi) {
        #pragma unroll
        for (int n8 = 0; n8 < 4; ++n8) {
            int col = n0 + nw + n8 * 8 + t2;
            float b0 = bq[col], b1 = bq[col + 1];
            float q00 = acc[mi][n8][0] + b0; q00 *= q00;
            float q01 = acc[mi][n8][1] + b1; q01 *= q01;
            float q10 = acc[mi][n8][2] + b0; q10 *= q10;
            float q11 = acc[mi][n8][3] + b1; q11 *= q11;
            acc[mi][n8][0] = q00; acc[mi][n8][1] = q01;
            acc[mi][n8][2] = q10; acc[mi][n8][3] = q11;
            part[mi][0] += q00 * ks0[n8] + q01 * ks1[n8];
            part[mi][1] += q10 * ks0[n8] + q11 * ks1[n8];
        }
    }
    #pragma unroll
    for (int mi = 0; mi < 4; ++mi) {
        int tl0 = mw + mi * 16 + g;
        atomicAdd(&zred[tl0 * 2 + hloc], part[mi][0]);
        atomicAdd(&zred[(tl0 + 8) * 2 + hloc], part[mi][1]);
    }
    __syncthreads();

    // scale and emit fp16 pair A'' = 2^16 * z * qh2
    #pragma unroll
    for (int mi = 0; mi < 4; ++mi) {
        int tl0 = mw + mi * 16 + g;
        float z0 = OSCL / (zred[tl0 * 2 + hloc] + 1e-6f);
        float z1 = OSCL / (zred[(tl0 + 8) * 2 + hloc] + 1e-6f);
        int r0 = m0 + tl0;
        #pragma unroll
        for (int n8 = 0; n8 < 4; ++n8) {
            int colh = (nw & 32) + n8 * 8 + t2;
            // row r0
            {
                float a = acc[mi][n8][0] * z0, c = acc[mi][n8][1] * z0;
                uint32_t hh = pack_f16(a, c);
                float2 hf = __half22float2(*(half2*)&hh);
                uint32_t ll = pack_f16(a - hf.x, c - hf.y);
                size_t base = (size_t)r0 * K2 + h * NE + colh;
                *(uint32_t*)(Azq + base)        = hh;
                *(uint32_t*)(Azq + base + 1024) = ll;
            }
            // row r0+8
            {
                float a = acc[mi][n8][2] * z1, c = acc[mi][n8][3] * z1;
                uint32_t hh = pack_f16(a, c);
                float2 hf = __half22float2(*(half2*)&hh);
                uint32_t ll = pack_f16(a - hf.x, c - hf.y);
                size_t base = (size_t)(r0 + 8) * K2 + h * NE + colh;
                *(uint32_t*)(Azq + base)        = hh;
                *(uint32_t*)(Azq + base + 1024) = ll;
            }
        }
    }
}

// ---------------- O GEMM: out = (A'' x B''_b)*2^-16 + bo ----------------
__global__ void __launch_bounds__(256, 2) gemm_o(
    const unsigned short* __restrict__ A2, const unsigned short* __restrict__ B2o,
    const float* __restrict__ bo, float* __restrict__ out)
{
    extern __shared__ __align__(128) char smem[];
    const uint32_t sb = s2u(smem);
    const int tid = threadIdx.x, lane = tid & 31, wid = tid >> 5;
    const int m0 = blockIdx.y * BM, n0 = blockIdx.x * BN;
    const unsigned short* Bm = B2o + (size_t)(m0 >> 12) * ND * K2;

    float acc[4][4][4];
    #pragma unroll
    for (int i = 0; i < 4; ++i)
        #pragma unroll
        for (int j = 0; j < 4; ++j)
            #pragma unroll
            for (int r = 0; r < 4; ++r) acc[i][j][r] = 0.f;

    gemm_mainloop(sb, A2, Bm, m0, n0, tid, lane, wid, acc);

    const int g = lane >> 2, t2 = (lane & 3) * 2;
    const int mw = (wid >> 2) * 64, nw = (wid & 3) * 32;
    #pragma unroll
    for (int mi = 0; mi < 4; ++mi) {
        #pragma unroll
        for (int n8 = 0; n8 < 4; ++n8) {
            int col = n0 + nw + n8 * 8 + t2;
            float b0 = bo[col], b1 = bo[col + 1];
            int r0 = m0 + mw + mi * 16 + g;
            int r1 = r0 + 8;
            float2 v0 = make_float2(acc[mi][n8][0] * IOSCL + b0, acc[mi][n8][1] * IOSCL + b1);
            float2 v1 = make_float2(acc[mi][n8][2] * IOSCL + b0, acc[mi][n8][3] * IOSCL + b1);
            *(float2*)(out + (size_t)r0 * ND + col) = v0;
            *(float2*)(out + (size_t)r1 * ND + col) = v1;
        }
    }
}

// ---------------- kv_sum & k_sum ----------------
__global__ __launch_bounds__(256) void kvsum_partial(
    const float* __restrict__ kh2, const float* __restrict__ vh,
    float* __restrict__ kvp, float* __restrict__ ksp)
{
    int bh = blockIdx.x;
    int sp = blockIdx.y;
    const float* kb = kh2 + ((size_t)bh*NT + (size_t)sp*TCH)*NE;
    const float* vb = vh  + ((size_t)bh*NT + (size_t)sp*TCH)*NE;
    __shared__ float sk[16][NE];
    __shared__ float sv[16][NE];
    int tid = threadIdx.x;
    int d  = tid >> 2;
    int e0 = (tid & 3) << 4;
    float acc[16];
    #pragma unroll
    for (int j = 0; j < 16; ++j) acc[j] = 0.f;
    float ksacc = 0.f;

    for (int t0 = 0; t0 < TCH; t0 += 16) {
        #pragma unroll
        for (int i = 0; i < 4; ++i) {
            int idx = tid + i*256;
            ((float*)sk)[idx] = kb[(size_t)t0*NE + idx];
            ((float*)sv)[idx] = vb[(size_t)t0*NE + idx];
        }
        __syncthreads();
        #pragma unroll
        for (int tt = 0; tt < 16; ++tt) {
            float kval = sk[tt][d];
            ksacc += kval;
            #pragma unroll
            for (int j = 0; j < 16; ++j)
                acc[j] += kval * sv[tt][e0 + j];
        }
        __syncthreads();
    }
    float* outp = kvp + ((size_t)(bh*SPLITR + sp))*NE*NE + (size_t)d*NE + e0;
    #pragma unroll
    for (int j = 0; j < 16; ++j) outp[j] = acc[j];
    if ((tid & 3) == 0) ksp[(size_t)(bh*SPLITR + sp)*NE + d] = ksacc;
}

__global__ void kvsum_reduce(const float* __restrict__ kvp, const float* __restrict__ ksp,
                             float* __restrict__ kvs, float* __restrict__ kss)
{
    int bh = blockIdx.x;
    int tid = threadIdx.x;
    for (int i = tid; i < NE*NE; i += 256) {
        float s = 0.f;
        #pragma unroll
        for (int sp = 0; sp < SPLITR; ++sp)
            s += kvp[((size_t)(bh*SPLITR + sp))*NE*NE + i];
        kvs[(size_t)bh*NE*NE + i] = s;
    }
    if (tid < NE) {
        float s = 0.f;
        #pragma unroll
        for (int sp = 0; sp < SPLITR; ++sp)
            s += ksp[(size_t)(bh*SPLITR + sp)*NE + tid];
        kss[(size_t)bh*NE + tid] = s;
    }
}

// ---------------- B'' build: B''_b[n][h*64+d] = sum_e kvsum[b,h][d][e]*Wo[n][h*64+e]
__global__ __launch_bounds__(256) void buildB(
    const float* __restrict__ Wo, const float* __restrict__ kvs,
    unsigned short* __restrict__ B2o)
{
    int bh = blockIdx.y;
    int b = bh >> 4, h = bh & 15;
    int n0 = blockIdx.x * 64;
    __shared__ float skv[64][64];
    __shared__ float swo[64][65];
    int tid = threadIdx.x;
    for (int i = tid; i < 4096; i += 256)
        ((float*)skv)[i] = kvs[(size_t)bh*4096 + i];
    for (int i = tid; i < 4096; i += 256) {
        int n = i >> 6, e = i & 63;
        swo[n][e] = Wo[(size_t)(n0 + n) * ND + h * 64 + e];
    }
    __syncthreads();
    int n = tid & 63;
    int d0 = (tid >> 6) * 16;
    float acc[16];
    #pragma unroll
    for (int j = 0; j < 16; ++j) acc[j] = 0.f;
    for (int e = 0; e < 64; ++e) {
        float w = swo[n][e];
        #pragma unroll
        for (int j = 0; j < 16; ++j)
            acc[j] += w * skv[d0 + j][e];
    }
    size_t base = (size_t)b * ND * K2 + (size_t)(n0 + n) * K2 + h * 64 + d0;
    uint32_t pk[8];
    #pragma unroll
    for (int j = 0; j < 8; ++j) pk[j] = pack_f16(acc[2*j], acc[2*j+1]);
    *(uint4*)(&((unsigned short*)B2o)[base])        = *(uint4*)(pk);
    *(uint4*)(&((unsigned short*)B2o)[base + 8])    = *(uint4*)(pk + 4);
    *(uint4*)(&((unsigned short*)B2o)[base + 1024])     = *(uint4*)(pk);
    *(uint4*)(&((unsigned short*)B2o)[base + 1024 + 8]) = *(uint4*)(pk + 4);
}

// ---------------- launch ----------------
extern "C" void kernel_launch(void* const* d_in, const int* in_sizes, int n_in,
                              void* d_out, int out_size)
{
    const float* q  = (const float*)d_in[0];
    const float* kv = (const float*)d_in[1];
    const float* Wq = (const float*)d_in[2];
    const float* bq = (const float*)d_in[3];
    const float* Wk = (const float*)d_in[4];
    const float* bk = (const float*)d_in[5];
    const float* Wv = (const float*)d_in[6];
    const float* bv = (const float*)d_in[7];
    const float* Wo = (const float*)d_in[8];
    const float* bo = (const float*)d_in[9];
    float* out = (float*)d_out;

    unsigned short *Aq2, *Akv2, *Azq, *Bq2, *Bk2, *Bv2, *B2o;
    float *feat, *kvp, *ksp, *kvs, *kss;
    cudaGetSymbolAddress((void**)&Aq2,  g_Aq2);
    cudaGetSymbolAddress((void**)&Akv2, g_Akv2);
    cudaGetSymbolAddress((void**)&Azq,  g_Azq);
    cudaGetSymbolAddress((void**)&Bq2,  g_Bq2);
    cudaGetSymbolAddress((void**)&Bk2,  g_Bk2);
    cudaGetSymbolAddress((void**)&Bv2,  g_Bv2);
    cudaGetSymbolAddress((void**)&B2o,  g_B2o);
    cudaGetSymbolAddress((void**)&feat, g_feat);
    cudaGetSymbolAddress((void**)&kvp,  g_kvpart);
    cudaGetSymbolAddress((void**)&ksp,  g_kspart);
    cudaGetSymbolAddress((void**)&kvs,  g_kvsum);
    cudaGetSymbolAddress((void**)&kss,  g_ksum);

    float* fk = feat + 0*(size_t)NBH*NT*NE;
    float* fv = feat + 1*(size_t)NBH*NT*NE;

    cudaFuncSetAttribute((const void*)gemm_kv,     cudaFuncAttributeMaxDynamicSharedMemorySize, GEMM_SMEM);
    cudaFuncSetAttribute((const void*)gemm_qfused, cudaFuncAttributeMaxDynamicSharedMemorySize, GEMM_SMEM);
    cudaFuncSetAttribute((const void*)gemm_o,      cudaFuncAttributeMaxDynamicSharedMemorySize, GEMM_SMEM);

    // [0] activation splits (q and kv)
    {
        int n4 = NM*ND/4;
        int blk = (n4 + 255) / 256;
        split_pair<<<dim3(blk, 2), 256>>>((const float4*)q, (const float4*)kv, Aq2, Akv2);
    }
    // [1] weight prep (Wq, Wk, Wv)
    {
        int blk2 = (ND*ND + 255) / 256;
        wprep3<<<dim3(blk2, 3), 256>>>(Wq, Wk, Wv, Bq2, Bk2, Bv2);
    }
    // [2] K | V projection GEMMs
    {
        dim3 grid(ND / BN, NM / BM, 2);
        gemm_kv<<<grid, 256, GEMM_SMEM>>>(Akv2, Bk2, Bv2, bk, bv, fk, fv);
    }
    // [3][4] kv_sum / k_sum
    {
        dim3 grid(NBH, SPLITR);
        kvsum_partial<<<grid, 256>>>(fk, fv, kvp, ksp);
        kvsum_reduce<<<NBH, 256>>>(kvp, ksp, kvs, kss);
    }
    // [5] B'' = blockstack(kvsum_h * Wo_h^T) fp16 dup, per batch
    {
        dim3 grid(ND / 64, NBH);
        buildB<<<grid, 256>>>(Wo, kvs, B2o);
    }
    // [6] Q projection fused with z-scale -> A''
    {
        dim3 grid(ND / BN, NM / BM);
        gemm_qfused<<<grid, 256, GEMM_SMEM>>>(Aq2, Bq2, bq, kss, Azq);
    }
    // [7] output GEMM
    {
        dim3 grid(ND / BN, NM / BM);
        gemm_o<<<grid, 256, GEMM_SMEM>>>(Azq, B2o, bo, out);
    }
}

// round 8
// speedup vs baseline: 2.2629x; 1.2733x over previous
#include <cuda_runtime.h>
#include <cuda_bf16.h>
#include <cuda_fp16.h>
#include <cstdint>
#include <cstddef>

// ---------------- problem constants ----------------
#define NB 4
#define NT 4096
#define ND 1024
#define NH 16
#define NE 64
#define NBH (NB*NH)     // 64
#define NM (NB*NT)      // 16384
#define K2 2048         // fp16x2 packed K (all GEMMs)
#define SPLITR 8
#define TCH (NT/SPLITR) // 512

// ---------------- GEMM tiling ----------------
#define BM 128
#define BN 128
#define TILE_BYTES (BM*128)         // 16384
#define STAGE_BYTES (2*TILE_BYTES)  // 32768
#define STAGES 3
#define GEMM_SMEM (STAGES*STAGE_BYTES)  // 98304
#define NCH (K2/64)                 // 32
#define OSCL 65536.0f
#define IOSCL (1.0f/65536.0f)

// ---------------- scratch (device globals) ----------------
__device__ unsigned short g_Aq2[(size_t)NM*K2];   // q:  [hi | lo] fp16
__device__ unsigned short g_Akv2[(size_t)NM*K2];  // kv: [hi | lo] fp16
__device__ unsigned short g_Azq[(size_t)NM*K2];   // A'' = 2^16*z*qh2: [hi | lo] fp16
__device__ unsigned short g_Bq2[(size_t)ND*K2];   // Wq: [w | w] fp16
__device__ unsigned short g_Bk2[(size_t)ND*K2];   // Wk: [w | w] fp16
__device__ unsigned short g_Bv2[(size_t)ND*K2];   // Wv: [w | w] fp16
__device__ unsigned short g_B2o[(size_t)NB*ND*K2];// B'' per batch: [w | w] fp16
__device__ float g_feat[2][(size_t)NBH*NT*NE];    // kh2, vh in [b,h,t,e]
__device__ float g_kvpart[(size_t)NBH*SPLITR*NE*NE];
__device__ float g_kspart[(size_t)NBH*SPLITR*NE];
__device__ float g_kvsum[(size_t)NBH*NE*NE];
__device__ float g_ksum[(size_t)NBH*NE];

// ---------------- helpers ----------------
__device__ __forceinline__ uint32_t s2u(const void* p) {
    uint32_t a;
    asm("{ .reg .u64 t; cvta.to.shared.u64 t, %1; cvt.u32.u64 %0, t; }" : "=r"(a) : "l"(p));
    return a;
}
__device__ __forceinline__ uint32_t swz(uint32_t b) { return b ^ ((b >> 3) & 0x70); }

__device__ __forceinline__ void cpasync16(uint32_t dst, const void* src) {
    asm volatile("cp.async.cg.shared.global [%0], [%1], 16;" :: "r"(dst), "l"(src));
}
__device__ __forceinline__ void cp_commit() {
    asm volatile("cp.async.commit_group;" ::: "memory");
}
template<int N>
__device__ __forceinline__ void cp_wait() {
    asm volatile("cp.async.wait_group %0;" :: "n"(N) : "memory");
}
__device__ __forceinline__ void ldsm4(uint32_t* r, uint32_t addr) {
    asm volatile("ldmatrix.sync.aligned.m8n8.x4.shared.b16 {%0,%1,%2,%3}, [%4];"
                 : "=r"(r[0]), "=r"(r[1]), "=r"(r[2]), "=r"(r[3]) : "r"(addr));
}
__device__ __forceinline__ void mma_fp16(float* c, const uint32_t* a, const uint32_t* b) {
    asm volatile(
        "mma.sync.aligned.m16n8k16.row.col.f32.f16.f16.f32 "
        "{%0,%1,%2,%3}, {%4,%5,%6,%7}, {%8,%9}, {%0,%1,%2,%3};"
        : "+f"(c[0]), "+f"(c[1]), "+f"(c[2]), "+f"(c[3])
        : "r"(a[0]), "r"(a[1]), "r"(a[2]), "r"(a[3]), "r"(b[0]), "r"(b[1]));
}
__device__ __forceinline__ uint32_t pack_f16(float a, float b) {   // ushort2(h(a), h(b))
    uint32_t r;
    asm("cvt.rn.f16x2.f32 %0, %1, %2;" : "=r"(r) : "f"(b), "f"(a));
    return r;
}

// ---------------- prep kernels ----------------
// x -> fp16 pair [hi | lo] ; grid.y selects (q -> Aq2) / (kv -> Akv2)
__global__ void split_pair(const float4* __restrict__ xq, const float4* __restrict__ xkv,
                           unsigned short* __restrict__ Aq2, unsigned short* __restrict__ Akv2) {
    int gi = blockIdx.x * blockDim.x + threadIdx.x;
    if (gi >= NM*ND/4) return;
    const float4* x = (blockIdx.y == 0) ? xq : xkv;
    unsigned short* A2 = (blockIdx.y == 0) ? Aq2 : Akv2;
    int m = gi >> 8;
    int kq = (gi & 255) << 2;
    float4 v = x[gi];
    uint32_t p01 = pack_f16(v.x, v.y);
    uint32_t p23 = pack_f16(v.z, v.w);
    float2 f01 = __half22float2(*(half2*)&p01);
    float2 f23 = __half22float2(*(half2*)&p23);
    uint32_t q01 = pack_f16(v.x - f01.x, v.y - f01.y);
    uint32_t q23 = pack_f16(v.z - f23.x, v.w - f23.y);
    unsigned short* row = A2 + (size_t)m * K2;
    *(uint2*)(row + kq)        = make_uint2(p01, p23);
    *(uint2*)(row + 1024 + kq) = make_uint2(q01, q23);
}
// weight prep: y in {0,1,2} -> Wq,Wk,Wv as fp16 dup [w | w], B[n][k], n=h*64+e
__global__ void wprep3(const float* __restrict__ Wq, const float* __restrict__ Wk,
                       const float* __restrict__ Wv,
                       unsigned short* __restrict__ Bq2, unsigned short* __restrict__ Bk2,
                       unsigned short* __restrict__ Bv2) {
    int idx = blockIdx.x * blockDim.x + threadIdx.x;
    if (idx >= ND*ND) return;
    int which = blockIdx.y;
    int n = idx >> 10, k = idx & 1023;
    const float* W = (which == 0) ? Wq : (which == 1) ? Wk : Wv;
    float v = W[((size_t)(n >> 6) * ND + k) * NE + (n & 63)];
    unsigned short h = __half_as_ushort(__float2half_rn(v));
    unsigned short* row = ((which == 0) ? Bq2 : (which == 1) ? Bk2 : Bv2) + (size_t)n * K2;
    row[k] = h; row[1024 + k] = h;
}

// ---------------- shared fp16 GEMM mainloop (K fixed = K2) ----------------
__device__ __forceinline__ void gemm_mainloop(
    uint32_t sb, const unsigned short* __restrict__ A, const unsigned short* __restrict__ Bm,
    int m0, int n0, int tid, int lane, int wid, float acc[4][4][4])
{
    const int lrow = tid >> 3, lkc = tid & 7;
    const int mw = (wid >> 2) * 64, nw = (wid & 3) * 32;
    const int arow = mw + (lane & 15);
    const int brow = nw + (lane & 7) + ((lane >> 4) & 1) * 8;

    #pragma unroll
    for (int s = 0; s < STAGES - 1; ++s) {
        uint32_t sA = sb + s * STAGE_BYTES, sB = sA + TILE_BYTES;
        int k0 = s * 64;
        #pragma unroll
        for (int i = 0; i < 4; ++i) {
            int row = lrow + i * 32;
            uint32_t so = swz(row * 128 + lkc * 16);
            cpasync16(sA + so, A  + (size_t)(m0 + row) * K2 + k0 + lkc * 8);
            cpasync16(sB + so, Bm + (size_t)(n0 + row) * K2 + k0 + lkc * 8);
        }
        cp_commit();
    }
    for (int ch = 0; ch < NCH; ++ch) {
        cp_wait<STAGES - 2>();
        __syncthreads();
        int chn = ch + STAGES - 1;
        if (chn < NCH) {
            int sl = chn % STAGES;
            uint32_t sA = sb + sl * STAGE_BYTES, sB = sA + TILE_BYTES;
            int k0 = chn * 64;
            #pragma unroll
            for (int i = 0; i < 4; ++i) {
                int row = lrow + i * 32;
                uint32_t so = swz(row * 128 + lkc * 16);
                cpasync16(sA + so, A  + (size_t)(m0 + row) * K2 + k0 + lkc * 8);
                cpasync16(sB + so, Bm + (size_t)(n0 + row) * K2 + k0 + lkc * 8);
            }
        }
        cp_commit();
        const int s = ch % STAGES;
        const uint32_t aBase = sb + s * STAGE_BYTES;
        const uint32_t bBase = aBase + TILE_BYTES;
        #pragma unroll
        for (int k16 = 0; k16 < 4; ++k16) {
            uint32_t a[4][4], bf[2][4];
            const int acol = (k16 * 16 + (lane >> 4) * 8) * 2;
            const int bcol = (k16 * 16 + ((lane >> 3) & 1) * 8) * 2;
            #pragma unroll
            for (int mi = 0; mi < 4; ++mi)
                ldsm4(a[mi], aBase + swz((arow + mi * 16) * 128 + acol));
            #pragma unroll
            for (int nj = 0; nj < 2; ++nj)
                ldsm4(bf[nj], bBase + swz((brow + nj * 16) * 128 + bcol));
            #pragma unroll
            for (int mi = 0; mi < 4; ++mi)
                #pragma unroll
                for (int n8 = 0; n8 < 4; ++n8)
                    mma_fp16(acc[mi][n8], a[mi], &bf[n8 >> 1][(n8 & 1) * 2]);
        }
    }
}

// ---------------- K|V projection GEMM (blockIdx.z: 0=K squared, 1=V) --------
__global__ void __launch_bounds__(256, 2) gemm_kv(
    const unsigned short* __restrict__ Akv,
    const unsigned short* __restrict__ Bk, const unsigned short* __restrict__ Bv,
    const float* __restrict__ bk, const float* __restrict__ bv,
    float* __restrict__ fk, float* __restrict__ fv)
{
    extern __shared__ __align__(128) char smem[];
    const uint32_t sb = s2u(smem);
    const int tid = threadIdx.x, lane = tid & 31, wid = tid >> 5;
    const int m0 = blockIdx.y * BM, n0 = blockIdx.x * BN;
    const int which = blockIdx.z;
    const unsigned short* Bm = (which == 0) ? Bk : Bv;
    const float* bias = (which == 0) ? bk : bv;
    float* C = (which == 0) ? fk : fv;

    float acc[4][4][4];
    #pragma unroll
    for (int i = 0; i < 4; ++i)
        #pragma unroll
        for (int j = 0; j < 4; ++j)
            #pragma unroll
            for (int r = 0; r < 4; ++r) acc[i][j][r] = 0.f;

    gemm_mainloop(sb, Akv, Bm, m0, n0, tid, lane, wid, acc);

    const int g = lane >> 2, t2 = (lane & 3) * 2;
    const int mw = (wid >> 2) * 64, nw = (wid & 3) * 32;
    #pragma unroll
    for (int mi = 0; mi < 4; ++mi) {
        #pragma unroll
        for (int n8 = 0; n8 < 4; ++n8) {
            int col = n0 + nw + n8 * 8 + t2;
            float b0 = bias[col], b1 = bias[col + 1];
            int r0 = m0 + mw + mi * 16 + g;
            int r1 = r0 + 8;
            float2 v0 = make_float2(acc[mi][n8][0] + b0, acc[mi][n8][1] + b1);
            float2 v1 = make_float2(acc[mi][n8][2] + b0, acc[mi][n8][3] + b1);
            if (which == 0) { v0.x *= v0.x; v0.y *= v0.y; v1.x *= v1.x; v1.y *= v1.y; }
            int h = col >> 6, e = col & 63;
            int b_0 = r0 >> 12, t_0 = r0 & (NT - 1);
            int b_1 = r1 >> 12, t_1 = r1 & (NT - 1);
            *(float2*)(C + ((((size_t)b_0 * NH + h) * NT + t_0) * NE + e)) = v0;
            *(float2*)(C + ((((size_t)b_1 * NH + h) * NT + t_1) * NE + e)) = v1;
        }
    }
}

// ---------------- Q projection GEMM fused with z-scale -> A'' ---------------
__global__ void __launch_bounds__(256, 2) gemm_qfused(
    const unsigned short* __restrict__ Aq, const unsigned short* __restrict__ Bq,
    const float* __restrict__ bq, const float* __restrict__ kss,
    unsigned short* __restrict__ Azq)
{
    extern __shared__ __align__(128) char smem[];
    const uint32_t sb = s2u(smem);
    const int tid = threadIdx.x, lane = tid & 31, wid = tid >> 5;
    const int m0 = blockIdx.y * BM, n0 = blockIdx.x * BN;

    float acc[4][4][4];
    #pragma unroll
    for (int i = 0; i < 4; ++i)
        #pragma unroll
        for (int j = 0; j < 4; ++j)
            #pragma unroll
            for (int r = 0; r < 4; ++r) acc[i][j][r] = 0.f;

    gemm_mainloop(sb, Aq, Bq, m0, n0, tid, lane, wid, acc);

    const int g = lane >> 2, t2 = (lane & 3) * 2;
    const int mw = (wid >> 2) * 64, nw = (wid & 3) * 32;
    const int b = m0 >> 12;
    const int hloc = nw >> 6;                 // 0 or 1
    const int h = (n0 >> 6) + hloc;           // global head 0..15
    const int bh = b * NH + h;

    float ks0[4], ks1[4];
    #pragma unroll
    for (int n8 = 0; n8 < 4; ++n8) {
        int colh = (nw & 32) + n8 * 8 + t2;
        ks0[n8] = kss[bh * NE + colh];
        ks1[n8] = kss[bh * NE + colh + 1];
    }

    float* zred = (float*)smem;               // 256 floats: [t_local][head_local]
    __syncthreads();
    if (tid < 256) zred[tid] = 0.f;
    __syncthreads();

    float part[4][2];
    #pragma unroll
    for (int mi = 0; mi < 4; ++mi) { part[mi][0] = 0.f; part[mi][1] = 0.f; }
    #pragma unroll
    for (int mi = 0; mi < 4; ++mi) {
        #pragma unroll
        for (int n8 = 0; n8 < 4; ++n8) {
            int col = n0 + nw + n8 * 8 + t2;
            float b0 = bq[col], b1 = bq[col + 1];
            float q00 = acc[mi][n8][0] + b0; q00 *= q00;
            float q01 = acc[mi][n8][1] + b1; q01 *= q01;
            float q10 = acc[mi][n8][2] + b0; q10 *= q10;
            float q11 = acc[mi][n8][3] + b1; q11 *= q11;
            acc[mi][n8][0] = q00; acc[mi][n8][1] = q01;
            acc[mi][n8][2] = q10; acc[mi][n8][3] = q11;
            part[mi][0] += q00 * ks0[n8] + q01 * ks1[n8];
            part[mi][1] += q10 * ks0[n8] + q11 * ks1[n8];
        }
    }
    #pragma unroll
    for (int mi = 0; mi < 4; ++mi) {
        int tl0 = mw + mi * 16 + g;
        atomicAdd(&zred[tl0 * 2 + hloc], part[mi][0]);
        atomicAdd(&zred[(tl0 + 8) * 2 + hloc], part[mi][1]);
    }
    __syncthreads();

    #pragma unroll
    for (int mi = 0; mi < 4; ++mi) {
        int tl0 = mw + mi * 16 + g;
        float z0 = OSCL / (zred[tl0 * 2 + hloc] + 1e-6f);
        float z1 = OSCL / (zred[(tl0 + 8) * 2 + hloc] + 1e-6f);
        int r0 = m0 + tl0;
        #pragma unroll
        for (int n8 = 0; n8 < 4; ++n8) {
            int colh = (nw & 32) + n8 * 8 + t2;
            {
                float a = acc[mi][n8][0] * z0, c = acc[mi][n8][1] * z0;
                uint32_t hh = pack_f16(a, c);
                float2 hf = __half22float2(*(half2*)&hh);
                uint32_t ll = pack_f16(a - hf.x, c - hf.y);
                size_t base = (size_t)r0 * K2 + h * NE + colh;
                *(uint32_t*)(Azq + base)        = hh;
                *(uint32_t*)(Azq + base + 1024) = ll;
            }
            {
                float a = acc[mi][n8][2] * z1, c = acc[mi][n8][3] * z1;
                uint32_t hh = pack_f16(a, c);
                float2 hf = __half22float2(*(half2*)&hh);
                uint32_t ll = pack_f16(a - hf.x, c - hf.y);
                size_t base = (size_t)(r0 + 8) * K2 + h * NE + colh;
                *(uint32_t*)(Azq + base)        = hh;
                *(uint32_t*)(Azq + base + 1024) = ll;
            }
        }
    }
}

// ---------------- O GEMM: out = (A'' x B''_b)*2^-16 + bo ----------------
__global__ void __launch_bounds__(256, 2) gemm_o(
    const unsigned short* __restrict__ A2, const unsigned short* __restrict__ B2o,
    const float* __restrict__ bo, float* __restrict__ out)
{
    extern __shared__ __align__(128) char smem[];
    const uint32_t sb = s2u(smem);
    const int tid = threadIdx.x, lane = tid & 31, wid = tid >> 5;
    const int m0 = blockIdx.y * BM, n0 = blockIdx.x * BN;
    const unsigned short* Bm = B2o + (size_t)(m0 >> 12) * ND * K2;

    float acc[4][4][4];
    #pragma unroll
    for (int i = 0; i < 4; ++i)
        #pragma unroll
        for (int j = 0; j < 4; ++j)
            #pragma unroll
            for (int r = 0; r < 4; ++r) acc[i][j][r] = 0.f;

    gemm_mainloop(sb, A2, Bm, m0, n0, tid, lane, wid, acc);

    const int g = lane >> 2, t2 = (lane & 3) * 2;
    const int mw = (wid >> 2) * 64, nw = (wid & 3) * 32;
    #pragma unroll
    for (int mi = 0; mi < 4; ++mi) {
        #pragma unroll
        for (int n8 = 0; n8 < 4; ++n8) {
            int col = n0 + nw + n8 * 8 + t2;
            float b0 = bo[col], b1 = bo[col + 1];
            int r0 = m0 + mw + mi * 16 + g;
            int r1 = r0 + 8;
            float2 v0 = make_float2(acc[mi][n8][0] * IOSCL + b0, acc[mi][n8][1] * IOSCL + b1);
            float2 v1 = make_float2(acc[mi][n8][2] * IOSCL + b0, acc[mi][n8][3] * IOSCL + b1);
            *(float2*)(out + (size_t)r0 * ND + col) = v0;
            *(float2*)(out + (size_t)r1 * ND + col) = v1;
        }
    }
}

// ---------------- kv_sum & k_sum: 4d x 4e register tile per thread ----------
__global__ __launch_bounds__(256) void kvsum_partial(
    const float* __restrict__ kh2, const float* __restrict__ vh,
    float* __restrict__ kvp, float* __restrict__ ksp)
{
    int bh = blockIdx.x;
    int sp = blockIdx.y;
    const float* kb = kh2 + ((size_t)bh*NT + (size_t)sp*TCH)*NE;
    const float* vb = vh  + ((size_t)bh*NT + (size_t)sp*TCH)*NE;
    __shared__ float sk[32][NE];
    __shared__ float sv[32][NE];
    int tid = threadIdx.x;
    int d0 = (tid >> 4) << 2;    // 0,4,...,60
    int e0 = (tid & 15) << 2;    // 0,4,...,60
    bool doks = (tid & 15) == 0;

    float acc[4][4];
    #pragma unroll
    for (int i = 0; i < 4; ++i)
        #pragma unroll
        for (int j = 0; j < 4; ++j) acc[i][j] = 0.f;
    float ks[4] = {0.f, 0.f, 0.f, 0.f};

    for (int t0 = 0; t0 < TCH; t0 += 32) {
        // 32 rows x 64 floats = 512 float4 per array; 2 per thread
        const float4* gk = (const float4*)(kb + (size_t)t0 * NE);
        const float4* gv = (const float4*)(vb + (size_t)t0 * NE);
        #pragma unroll
        for (int i = 0; i < 2; ++i) {
            int idx = tid + i * 256;
            ((float4*)sk)[idx] = gk[idx];
            ((float4*)sv)[idx] = gv[idx];
        }
        __syncthreads();
        #pragma unroll
        for (int tt = 0; tt < 32; ++tt) {
            float4 kq = *(const float4*)&sk[tt][d0];
            float4 vq = *(const float4*)&sv[tt][e0];
            float kr[4] = {kq.x, kq.y, kq.z, kq.w};
            float vr[4] = {vq.x, vq.y, vq.z, vq.w};
            #pragma unroll
            for (int i = 0; i < 4; ++i)
                #pragma unroll
                for (int j = 0; j < 4; ++j)
                    acc[i][j] += kr[i] * vr[j];
            if (doks) {
                ks[0] += kr[0]; ks[1] += kr[1]; ks[2] += kr[2]; ks[3] += kr[3];
            }
        }
        __syncthreads();
    }
    float* outp = kvp + ((size_t)(bh*SPLITR + sp))*NE*NE;
    #pragma unroll
    for (int i = 0; i < 4; ++i)
        *(float4*)&outp[(size_t)(d0 + i)*NE + e0] =
            make_float4(acc[i][0], acc[i][1], acc[i][2], acc[i][3]);
    if (doks)
        *(float4*)&ksp[(size_t)(bh*SPLITR + sp)*NE + d0] =
            make_float4(ks[0], ks[1], ks[2], ks[3]);
}

__global__ void kvsum_reduce(const float* __restrict__ kvp, const float* __restrict__ ksp,
                             float* __restrict__ kvs, float* __restrict__ kss)
{
    int bh = blockIdx.x;
    int tid = threadIdx.x;
    for (int i = tid; i < NE*NE; i += 256) {
        float s = 0.f;
        #pragma unroll
        for (int sp = 0; sp < SPLITR; ++sp)
            s += kvp[((size_t)(bh*SPLITR + sp))*NE*NE + i];
        kvs[(size_t)bh*NE*NE + i] = s;
    }
    if (tid < NE) {
        float s = 0.f;
        #pragma unroll
        for (int sp = 0; sp < SPLITR; ++sp)
            s += ksp[(size_t)(bh*SPLITR + sp)*NE + tid];
        kss[(size_t)bh*NE + tid] = s;
    }
}

// ---------------- B'' build: B''_b[n][h*64+d] = sum_e kvsum[b,h][d][e]*Wo[n][h*64+e]
__global__ __launch_bounds__(256) void buildB(
    const float* __restrict__ Wo, const float* __restrict__ kvs,
    unsigned short* __restrict__ B2o)
{
    int bh = blockIdx.y;
    int b = bh >> 4, h = bh & 15;
    int n0 = blockIdx.x * 64;
    __shared__ float skv[64][64];
    __shared__ float swo[64][65];
    int tid = threadIdx.x;
    for (int i = tid; i < 4096; i += 256)
        ((float*)skv)[i] = kvs[(size_t)bh*4096 + i];
    for (int i = tid; i < 4096; i += 256) {
        int n = i >> 6, e = i & 63;
        swo[n][e] = Wo[(size_t)(n0 + n) * ND + h * 64 + e];
    }
    __syncthreads();
    int n = tid & 63;
    int d0 = (tid >> 6) * 16;
    float acc[16];
    #pragma unroll
    for (int j = 0; j < 16; ++j) acc[j] = 0.f;
    for (int e = 0; e < 64; ++e) {
        float w = swo[n][e];
        #pragma unroll
        for (int j = 0; j < 16; ++j)
            acc[j] += w * skv[d0 + j][e];
    }
    size_t base = (size_t)b * ND * K2 + (size_t)(n0 + n) * K2 + h * 64 + d0;
    uint32_t pk[8];
    #pragma unroll
    for (int j = 0; j < 8; ++j) pk[j] = pack_f16(acc[2*j], acc[2*j+1]);
    *(uint4*)(&((unsigned short*)B2o)[base])        = *(uint4*)(pk);
    *(uint4*)(&((unsigned short*)B2o)[base + 8])    = *(uint4*)(pk + 4);
    *(uint4*)(&((unsigned short*)B2o)[base + 1024])     = *(uint4*)(pk);
    *(uint4*)(&((unsigned short*)B2o)[base + 1024 + 8]) = *(uint4*)(pk + 4);
}

// ---------------- launch ----------------
extern "C" void kernel_launch(void* const* d_in, const int* in_sizes, int n_in,
                              void* d_out, int out_size)
{
    const float* q  = (const float*)d_in[0];
    const float* kv = (const float*)d_in[1];
    const float* Wq = (const float*)d_in[2];
    const float* bq = (const float*)d_in[3];
    const float* Wk = (const float*)d_in[4];
    const float* bk = (const float*)d_in[5];
    const float* Wv = (const float*)d_in[6];
    const float* bv = (const float*)d_in[7];
    const float* Wo = (const float*)d_in[8];
    const float* bo = (const float*)d_in[9];
    float* out = (float*)d_out;

    unsigned short *Aq2, *Akv2, *Azq, *Bq2, *Bk2, *Bv2, *B2o;
    float *feat, *kvp, *ksp, *kvs, *kss;
    cudaGetSymbolAddress((void**)&Aq2,  g_Aq2);
    cudaGetSymbolAddress((void**)&Akv2, g_Akv2);
    cudaGetSymbolAddress((void**)&Azq,  g_Azq);
    cudaGetSymbolAddress((void**)&Bq2,  g_Bq2);
    cudaGetSymbolAddress((void**)&Bk2,  g_Bk2);
    cudaGetSymbolAddress((void**)&Bv2,  g_Bv2);
    cudaGetSymbolAddress((void**)&B2o,  g_B2o);
    cudaGetSymbolAddress((void**)&feat, g_feat);
    cudaGetSymbolAddress((void**)&kvp,  g_kvpart);
    cudaGetSymbolAddress((void**)&ksp,  g_kspart);
    cudaGetSymbolAddress((void**)&kvs,  g_kvsum);
    cudaGetSymbolAddress((void**)&kss,  g_ksum);

    float* fk = feat + 0*(size_t)NBH*NT*NE;
    float* fv = feat + 1*(size_t)NBH*NT*NE;

    cudaFuncSetAttribute((const void*)gemm_kv,     cudaFuncAttributeMaxDynamicSharedMemorySize, GEMM_SMEM);
    cudaFuncSetAttribute((const void*)gemm_qfused, cudaFuncAttributeMaxDynamicSharedMemorySize, GEMM_SMEM);
    cudaFuncSetAttribute((const void*)gemm_o,      cudaFuncAttributeMaxDynamicSharedMemorySize, GEMM_SMEM);

    // [0] activation splits (q and kv)
    {
        int n4 = NM*ND/4;
        int blk = (n4 + 255) / 256;
        split_pair<<<dim3(blk, 2), 256>>>((const float4*)q, (const float4*)kv, Aq2, Akv2);
    }
    // [1] weight prep (Wq, Wk, Wv)
    {
        int blk2 = (ND*ND + 255) / 256;
        wprep3<<<dim3(blk2, 3), 256>>>(Wq, Wk, Wv, Bq2, Bk2, Bv2);
    }
    // [2] K | V projection GEMMs
    {
        dim3 grid(ND / BN, NM / BM, 2);
        gemm_kv<<<grid, 256, GEMM_SMEM>>>(Akv2, Bk2, Bv2, bk, bv, fk, fv);
    }
    // [3][4] kv_sum / k_sum
    {
        dim3 grid(NBH, SPLITR);
        kvsum_partial<<<grid, 256>>>(fk, fv, kvp, ksp);
        kvsum_reduce<<<NBH, 256>>>(kvp, ksp, kvs, kss);
    }
    // [5] B'' = blockstack(kvsum_h * Wo_h^T) fp16 dup, per batch
    {
        dim3 grid(ND / 64, NBH);
        buildB<<<grid, 256>>>(Wo, kvs, B2o);
    }
    // [6] Q projection fused with z-scale -> A''
    {
        dim3 grid(ND / BN, NM / BM);
        gemm_qfused<<<grid, 256, GEMM_SMEM>>>(Aq2, Bq2, bq, kss, Azq);
    }
    // [7] output GEMM
    {
        dim3 grid(ND / BN, NM / BM);
        gemm_o<<<grid, 256, GEMM_SMEM>>>(Azq, B2o, bo, out);
    }
}

// round 9
// speedup vs baseline: 3.5774x; 1.5809x over previous
#include <cuda_runtime.h>
#include <cuda_bf16.h>
#include <cuda_fp16.h>
#include <cstdint>
#include <cstddef>

// ---------------- problem constants ----------------
#define NB 4
#define NT 4096
#define ND 1024
#define NH 16
#define NE 64
#define NBH (NB*NH)     // 64
#define NM (NB*NT)      // 16384
#define KK 1024         // plain fp16 K (all GEMMs)
#define SPLITR 8
#define TCH (NT/SPLITR) // 512

// ---------------- GEMM tiling ----------------
#define BM 128
#define BN 128
#define TILE_BYTES (BM*128)         // 16384
#define STAGE_BYTES (2*TILE_BYTES)  // 32768
#define STAGES 3
#define GEMM_SMEM (STAGES*STAGE_BYTES)  // 98304
#define NCH (KK/64)                 // 16
#define OSCL 65536.0f
#define IOSCL (1.0f/65536.0f)

// ---------------- scratch (device globals) ----------------
__device__ unsigned short g_Aq[(size_t)NM*KK];    // q fp16
__device__ unsigned short g_Akv[(size_t)NM*KK];   // kv fp16
__device__ unsigned short g_Azq[(size_t)NM*KK];   // A'' = 2^16*z*qh2 fp16
__device__ unsigned short g_Bq[(size_t)ND*KK];    // Wq fp16 [n][k]
__device__ unsigned short g_Bk[(size_t)ND*KK];    // Wk fp16 [n][k]
__device__ unsigned short g_Bv[(size_t)ND*KK];    // Wv fp16 [n][k]
__device__ unsigned short g_B2o[(size_t)NB*ND*KK];// B'' per batch fp16 [n][k]
__device__ unsigned short g_feat[2][(size_t)NBH*NT*NE]; // kh2, vh fp16 [b,h,t,e]
__device__ float g_kvpart[(size_t)NBH*SPLITR*NE*NE];
__device__ float g_kspart[(size_t)NBH*SPLITR*NE];
__device__ float g_kvsum[(size_t)NBH*NE*NE];
__device__ float g_ksum[(size_t)NBH*NE];

// ---------------- helpers ----------------
__device__ __forceinline__ uint32_t s2u(const void* p) {
    uint32_t a;
    asm("{ .reg .u64 t; cvta.to.shared.u64 t, %1; cvt.u32.u64 %0, t; }" : "=r"(a) : "l"(p));
    return a;
}
__device__ __forceinline__ uint32_t swz(uint32_t b) { return b ^ ((b >> 3) & 0x70); }

__device__ __forceinline__ void cpasync16(uint32_t dst, const void* src) {
    asm volatile("cp.async.cg.shared.global [%0], [%1], 16;" :: "r"(dst), "l"(src));
}
__device__ __forceinline__ void cp_commit() {
    asm volatile("cp.async.commit_group;" ::: "memory");
}
template<int N>
__device__ __forceinline__ void cp_wait() {
    asm volatile("cp.async.wait_group %0;" :: "n"(N) : "memory");
}
__device__ __forceinline__ void ldsm4(uint32_t* r, uint32_t addr) {
    asm volatile("ldmatrix.sync.aligned.m8n8.x4.shared.b16 {%0,%1,%2,%3}, [%4];"
                 : "=r"(r[0]), "=r"(r[1]), "=r"(r[2]), "=r"(r[3]) : "r"(addr));
}
__device__ __forceinline__ void mma_fp16(float* c, const uint32_t* a, const uint32_t* b) {
    asm volatile(
        "mma.sync.aligned.m16n8k16.row.col.f32.f16.f16.f32 "
        "{%0,%1,%2,%3}, {%4,%5,%6,%7}, {%8,%9}, {%0,%1,%2,%3};"
        : "+f"(c[0]), "+f"(c[1]), "+f"(c[2]), "+f"(c[3])
        : "r"(a[0]), "r"(a[1]), "r"(a[2]), "r"(a[3]), "r"(b[0]), "r"(b[1]));
}
__device__ __forceinline__ uint32_t pack_f16(float a, float b) {   // ushort2(h(a), h(b))
    uint32_t r;
    asm("cvt.rn.f16x2.f32 %0, %1, %2;" : "=r"(r) : "f"(b), "f"(a));
    return r;
}
__device__ __forceinline__ void h8_to_f8(uint4 u, float* f) {
    float2 t;
    t = __half22float2(*(half2*)&u.x); f[0] = t.x; f[1] = t.y;
    t = __half22float2(*(half2*)&u.y); f[2] = t.x; f[3] = t.y;
    t = __half22float2(*(half2*)&u.z); f[4] = t.x; f[5] = t.y;
    t = __half22float2(*(half2*)&u.w); f[6] = t.x; f[7] = t.y;
}

// ---------------- prep kernels ----------------
// fp32 -> fp16 convert; grid.y selects (q -> Aq) / (kv -> Akv)
__global__ void split_pair(const float4* __restrict__ xq, const float4* __restrict__ xkv,
                           unsigned short* __restrict__ Aq, unsigned short* __restrict__ Akv) {
    int gi = blockIdx.x * blockDim.x + threadIdx.x;
    if (gi >= NM*ND/4) return;
    const float4* x = (blockIdx.y == 0) ? xq : xkv;
    unsigned short* A = (blockIdx.y == 0) ? Aq : Akv;
    float4 v = x[gi];
    uint32_t p01 = pack_f16(v.x, v.y);
    uint32_t p23 = pack_f16(v.z, v.w);
    *(uint2*)(A + (size_t)gi * 4) = make_uint2(p01, p23);
}
// weight prep: y in {0,1,2} -> Wq,Wk,Wv as fp16 [n][k], n=h*64+e
__global__ void wprep3(const float* __restrict__ Wq, const float* __restrict__ Wk,
                       const float* __restrict__ Wv,
                       unsigned short* __restrict__ Bq, unsigned short* __restrict__ Bk,
                       unsigned short* __restrict__ Bv) {
    int idx = blockIdx.x * blockDim.x + threadIdx.x;
    if (idx >= ND*ND) return;
    int which = blockIdx.y;
    int n = idx >> 10, k = idx & 1023;
    const float* W = (which == 0) ? Wq : (which == 1) ? Wk : Wv;
    float v = W[((size_t)(n >> 6) * ND + k) * NE + (n & 63)];
    unsigned short h = __half_as_ushort(__float2half_rn(v));
    (((which == 0) ? Bq : (which == 1) ? Bk : Bv))[idx] = h;
}

// ---------------- shared fp16 GEMM mainloop (K fixed = KK) ----------------
__device__ __forceinline__ void gemm_mainloop(
    uint32_t sb, const unsigned short* __restrict__ A, const unsigned short* __restrict__ Bm,
    int m0, int n0, int tid, int lane, int wid, float acc[4][4][4])
{
    const int lrow = tid >> 3, lkc = tid & 7;
    const int mw = (wid >> 2) * 64, nw = (wid & 3) * 32;
    const int arow = mw + (lane & 15);
    const int brow = nw + (lane & 7) + ((lane >> 4) & 1) * 8;

    #pragma unroll
    for (int s = 0; s < STAGES - 1; ++s) {
        uint32_t sA = sb + s * STAGE_BYTES, sB = sA + TILE_BYTES;
        int k0 = s * 64;
        #pragma unroll
        for (int i = 0; i < 4; ++i) {
            int row = lrow + i * 32;
            uint32_t so = swz(row * 128 + lkc * 16);
            cpasync16(sA + so, A  + (size_t)(m0 + row) * KK + k0 + lkc * 8);
            cpasync16(sB + so, Bm + (size_t)(n0 + row) * KK + k0 + lkc * 8);
        }
        cp_commit();
    }
    for (int ch = 0; ch < NCH; ++ch) {
        cp_wait<STAGES - 2>();
        __syncthreads();
        int chn = ch + STAGES - 1;
        if (chn < NCH) {
            int sl = chn % STAGES;
            uint32_t sA = sb + sl * STAGE_BYTES, sB = sA + TILE_BYTES;
            int k0 = chn * 64;
            #pragma unroll
            for (int i = 0; i < 4; ++i) {
                int row = lrow + i * 32;
                uint32_t so = swz(row * 128 + lkc * 16);
                cpasync16(sA + so, A  + (size_t)(m0 + row) * KK + k0 + lkc * 8);
                cpasync16(sB + so, Bm + (size_t)(n0 + row) * KK + k0 + lkc * 8);
            }
        }
        cp_commit();
        const int s = ch % STAGES;
        const uint32_t aBase = sb + s * STAGE_BYTES;
        const uint32_t bBase = aBase + TILE_BYTES;
        #pragma unroll
        for (int k16 = 0; k16 < 4; ++k16) {
            uint32_t a[4][4], bf[2][4];
            const int acol = (k16 * 16 + (lane >> 4) * 8) * 2;
            const int bcol = (k16 * 16 + ((lane >> 3) & 1) * 8) * 2;
            #pragma unroll
            for (int mi = 0; mi < 4; ++mi)
                ldsm4(a[mi], aBase + swz((arow + mi * 16) * 128 + acol));
            #pragma unroll
            for (int nj = 0; nj < 2; ++nj)
                ldsm4(bf[nj], bBase + swz((brow + nj * 16) * 128 + bcol));
            #pragma unroll
            for (int mi = 0; mi < 4; ++mi)
                #pragma unroll
                for (int n8 = 0; n8 < 4; ++n8)
                    mma_fp16(acc[mi][n8], a[mi], &bf[n8 >> 1][(n8 & 1) * 2]);
        }
    }
}

// ---------------- K|V projection GEMM (blockIdx.z: 0=K squared, 1=V) --------
// outputs fp16 feat [b,h,t,e]
__global__ void __launch_bounds__(256, 2) gemm_kv(
    const unsigned short* __restrict__ Akv,
    const unsigned short* __restrict__ Bk, const unsigned short* __restrict__ Bv,
    const float* __restrict__ bk, const float* __restrict__ bv,
    unsigned short* __restrict__ fk, unsigned short* __restrict__ fv)
{
    extern __shared__ __align__(128) char smem[];
    const uint32_t sb = s2u(smem);
    const int tid = threadIdx.x, lane = tid & 31, wid = tid >> 5;
    const int m0 = blockIdx.y * BM, n0 = blockIdx.x * BN;
    const int which = blockIdx.z;
    const unsigned short* Bm = (which == 0) ? Bk : Bv;
    const float* bias = (which == 0) ? bk : bv;
    unsigned short* C = (which == 0) ? fk : fv;

    float acc[4][4][4];
    #pragma unroll
    for (int i = 0; i < 4; ++i)
        #pragma unroll
        for (int j = 0; j < 4; ++j)
            #pragma unroll
            for (int r = 0; r < 4; ++r) acc[i][j][r] = 0.f;

    gemm_mainloop(sb, Akv, Bm, m0, n0, tid, lane, wid, acc);

    const int g = lane >> 2, t2 = (lane & 3) * 2;
    const int mw = (wid >> 2) * 64, nw = (wid & 3) * 32;
    #pragma unroll
    for (int mi = 0; mi < 4; ++mi) {
        #pragma unroll
        for (int n8 = 0; n8 < 4; ++n8) {
            int col = n0 + nw + n8 * 8 + t2;
            float b0 = bias[col], b1 = bias[col + 1];
            int r0 = m0 + mw + mi * 16 + g;
            int r1 = r0 + 8;
            float v00 = acc[mi][n8][0] + b0, v01 = acc[mi][n8][1] + b1;
            float v10 = acc[mi][n8][2] + b0, v11 = acc[mi][n8][3] + b1;
            if (which == 0) { v00 *= v00; v01 *= v01; v10 *= v10; v11 *= v11; }
            int h = col >> 6, e = col & 63;
            int b_0 = r0 >> 12, t_0 = r0 & (NT - 1);
            int b_1 = r1 >> 12, t_1 = r1 & (NT - 1);
            *(uint32_t*)(C + ((((size_t)b_0 * NH + h) * NT + t_0) * NE + e)) = pack_f16(v00, v01);
            *(uint32_t*)(C + ((((size_t)b_1 * NH + h) * NT + t_1) * NE + e)) = pack_f16(v10, v11);
        }
    }
}

// ---------------- Q projection GEMM fused with z-scale -> A'' ---------------
__global__ void __launch_bounds__(256, 2) gemm_qfused(
    const unsigned short* __restrict__ Aq, const unsigned short* __restrict__ Bq,
    const float* __restrict__ bq, const float* __restrict__ kss,
    unsigned short* __restrict__ Azq)
{
    extern __shared__ __align__(128) char smem[];
    const uint32_t sb = s2u(smem);
    const int tid = threadIdx.x, lane = tid & 31, wid = tid >> 5;
    const int m0 = blockIdx.y * BM, n0 = blockIdx.x * BN;

    float acc[4][4][4];
    #pragma unroll
    for (int i = 0; i < 4; ++i)
        #pragma unroll
        for (int j = 0; j < 4; ++j)
            #pragma unroll
            for (int r = 0; r < 4; ++r) acc[i][j][r] = 0.f;

    gemm_mainloop(sb, Aq, Bq, m0, n0, tid, lane, wid, acc);

    const int g = lane >> 2, t2 = (lane & 3) * 2;
    const int mw = (wid >> 2) * 64, nw = (wid & 3) * 32;
    const int b = m0 >> 12;
    const int hloc = nw >> 6;                 // 0 or 1
    const int h = (n0 >> 6) + hloc;           // global head
    const int bh = b * NH + h;

    float ks0[4], ks1[4];
    #pragma unroll
    for (int n8 = 0; n8 < 4; ++n8) {
        int colh = (nw & 32) + n8 * 8 + t2;
        ks0[n8] = kss[bh * NE + colh];
        ks1[n8] = kss[bh * NE + colh + 1];
    }

    float* zred = (float*)smem;               // 256 floats: [t_local][head_local]
    __syncthreads();
    if (tid < 256) zred[tid] = 0.f;
    __syncthreads();

    float part[4][2];
    #pragma unroll
    for (int mi = 0; mi < 4; ++mi) { part[mi][0] = 0.f; part[mi][1] = 0.f; }
    #pragma unroll
    for (int mi = 0; mi < 4; ++mi) {
        #pragma unroll
        for (int n8 = 0; n8 < 4; ++n8) {
            int col = n0 + nw + n8 * 8 + t2;
            float b0 = bq[col], b1 = bq[col + 1];
            float q00 = acc[mi][n8][0] + b0; q00 *= q00;
            float q01 = acc[mi][n8][1] + b1; q01 *= q01;
            float q10 = acc[mi][n8][2] + b0; q10 *= q10;
            float q11 = acc[mi][n8][3] + b1; q11 *= q11;
            acc[mi][n8][0] = q00; acc[mi][n8][1] = q01;
            acc[mi][n8][2] = q10; acc[mi][n8][3] = q11;
            part[mi][0] += q00 * ks0[n8] + q01 * ks1[n8];
            part[mi][1] += q10 * ks0[n8] + q11 * ks1[n8];
        }
    }
    #pragma unroll
    for (int mi = 0; mi < 4; ++mi) {
        int tl0 = mw + mi * 16 + g;
        atomicAdd(&zred[tl0 * 2 + hloc], part[mi][0]);
        atomicAdd(&zred[(tl0 + 8) * 2 + hloc], part[mi][1]);
    }
    __syncthreads();

    #pragma unroll
    for (int mi = 0; mi < 4; ++mi) {
        int tl0 = mw + mi * 16 + g;
        float z0 = OSCL / (zred[tl0 * 2 + hloc] + 1e-6f);
        float z1 = OSCL / (zred[(tl0 + 8) * 2 + hloc] + 1e-6f);
        int r0 = m0 + tl0;
        #pragma unroll
        for (int n8 = 0; n8 < 4; ++n8) {
            int colh = (nw & 32) + n8 * 8 + t2;
            *(uint32_t*)(Azq + (size_t)r0 * KK + h * NE + colh) =
                pack_f16(acc[mi][n8][0] * z0, acc[mi][n8][1] * z0);
            *(uint32_t*)(Azq + (size_t)(r0 + 8) * KK + h * NE + colh) =
                pack_f16(acc[mi][n8][2] * z1, acc[mi][n8][3] * z1);
        }
    }
}

// ---------------- O GEMM: out = (A'' x B''_b)*2^-16 + bo ----------------
__global__ void __launch_bounds__(256, 2) gemm_o(
    const unsigned short* __restrict__ A2, const unsigned short* __restrict__ B2o,
    const float* __restrict__ bo, float* __restrict__ out)
{
    extern __shared__ __align__(128) char smem[];
    const uint32_t sb = s2u(smem);
    const int tid = threadIdx.x, lane = tid & 31, wid = tid >> 5;
    const int m0 = blockIdx.y * BM, n0 = blockIdx.x * BN;
    const unsigned short* Bm = B2o + (size_t)(m0 >> 12) * ND * KK;

    float acc[4][4][4];
    #pragma unroll
    for (int i = 0; i < 4; ++i)
        #pragma unroll
        for (int j = 0; j < 4; ++j)
            #pragma unroll
            for (int r = 0; r < 4; ++r) acc[i][j][r] = 0.f;

    gemm_mainloop(sb, A2, Bm, m0, n0, tid, lane, wid, acc);

    const int g = lane >> 2, t2 = (lane & 3) * 2;
    const int mw = (wid >> 2) * 64, nw = (wid & 3) * 32;
    #pragma unroll
    for (int mi = 0; mi < 4; ++mi) {
        #pragma unroll
        for (int n8 = 0; n8 < 4; ++n8) {
            int col = n0 + nw + n8 * 8 + t2;
            float b0 = bo[col], b1 = bo[col + 1];
            int r0 = m0 + mw + mi * 16 + g;
            int r1 = r0 + 8;
            float2 v0 = make_float2(acc[mi][n8][0] * IOSCL + b0, acc[mi][n8][1] * IOSCL + b1);
            float2 v1 = make_float2(acc[mi][n8][2] * IOSCL + b0, acc[mi][n8][3] * IOSCL + b1);
            *(float2*)(out + (size_t)r0 * ND + col) = v0;
            *(float2*)(out + (size_t)r1 * ND + col) = v1;
        }
    }
}

// ---------------- kv_sum & k_sum: fp16 input, 4d x 4e register tile ---------
__global__ __launch_bounds__(256) void kvsum_partial(
    const unsigned short* __restrict__ kh2, const unsigned short* __restrict__ vh,
    float* __restrict__ kvp, float* __restrict__ ksp)
{
    int bh = blockIdx.x;
    int sp = blockIdx.y;
    const unsigned short* kb = kh2 + ((size_t)bh*NT + (size_t)sp*TCH)*NE;
    const unsigned short* vb = vh  + ((size_t)bh*NT + (size_t)sp*TCH)*NE;
    __shared__ float sk[32][NE];
    __shared__ float sv[32][NE];
    int tid = threadIdx.x;
    int d0 = (tid >> 4) << 2;    // 0,4,...,60
    int e0 = (tid & 15) << 2;    // 0,4,...,60
    bool doks = (tid & 15) == 0;

    float acc[4][4];
    #pragma unroll
    for (int i = 0; i < 4; ++i)
        #pragma unroll
        for (int j = 0; j < 4; ++j) acc[i][j] = 0.f;
    float ks[4] = {0.f, 0.f, 0.f, 0.f};

    for (int t0 = 0; t0 < TCH; t0 += 32) {
        // 32 rows x 64 halves = 2048 halves = 256 x 8-half vectors; 1 per thread per array
        uint4 ku = ((const uint4*)(kb + (size_t)t0 * NE))[tid];
        uint4 vu = ((const uint4*)(vb + (size_t)t0 * NE))[tid];
        float kf[8], vf[8];
        h8_to_f8(ku, kf);
        h8_to_f8(vu, vf);
        ((float4*)sk)[tid*2]   = make_float4(kf[0], kf[1], kf[2], kf[3]);
        ((float4*)sk)[tid*2+1] = make_float4(kf[4], kf[5], kf[6], kf[7]);
        ((float4*)sv)[tid*2]   = make_float4(vf[0], vf[1], vf[2], vf[3]);
        ((float4*)sv)[tid*2+1] = make_float4(vf[4], vf[5], vf[6], vf[7]);
        __syncthreads();
        #pragma unroll
        for (int tt = 0; tt < 32; ++tt) {
            float4 kq = *(const float4*)&sk[tt][d0];
            float4 vq = *(const float4*)&sv[tt][e0];
            float kr[4] = {kq.x, kq.y, kq.z, kq.w};
            float vr[4] = {vq.x, vq.y, vq.z, vq.w};
            #pragma unroll
            for (int i = 0; i < 4; ++i)
                #pragma unroll
                for (int j = 0; j < 4; ++j)
                    acc[i][j] += kr[i] * vr[j];
            if (doks) {
                ks[0] += kr[0]; ks[1] += kr[1]; ks[2] += kr[2]; ks[3] += kr[3];
            }
        }
        __syncthreads();
    }
    float* outp = kvp + ((size_t)(bh*SPLITR + sp))*NE*NE;
    #pragma unroll
    for (int i = 0; i < 4; ++i)
        *(float4*)&outp[(size_t)(d0 + i)*NE + e0] =
            make_float4(acc[i][0], acc[i][1], acc[i][2], acc[i][3]);
    if (doks)
        *(float4*)&ksp[(size_t)(bh*SPLITR + sp)*NE + d0] =
            make_float4(ks[0], ks[1], ks[2], ks[3]);
}

__global__ void kvsum_reduce(const float* __restrict__ kvp, const float* __restrict__ ksp,
                             float* __restrict__ kvs, float* __restrict__ kss)
{
    int bh = blockIdx.x;
    int tid = threadIdx.x;
    for (int i = tid; i < NE*NE; i += 256) {
        float s = 0.f;
        #pragma unroll
        for (int sp = 0; sp < SPLITR; ++sp)
            s += kvp[((size_t)(bh*SPLITR + sp))*NE*NE + i];
        kvs[(size_t)bh*NE*NE + i] = s;
    }
    if (tid < NE) {
        float s = 0.f;
        #pragma unroll
        for (int sp = 0; sp < SPLITR; ++sp)
            s += ksp[(size_t)(bh*SPLITR + sp)*NE + tid];
        kss[(size_t)bh*NE + tid] = s;
    }
}

// ---------------- B'' build: B''_b[n][h*64+d] = sum_e kvsum[b,h][d][e]*Wo[n][h*64+e]
__global__ __launch_bounds__(256) void buildB(
    const float* __restrict__ Wo, const float* __restrict__ kvs,
    unsigned short* __restrict__ B2o)
{
    int bh = blockIdx.y;
    int b = bh >> 4, h = bh & 15;
    int n0 = blockIdx.x * 64;
    __shared__ float skv[64][64];
    __shared__ float swo[64][65];
    int tid = threadIdx.x;
    for (int i = tid; i < 4096; i += 256)
        ((float*)skv)[i] = kvs[(size_t)bh*4096 + i];
    for (int i = tid; i < 4096; i += 256) {
        int n = i >> 6, e = i & 63;
        swo[n][e] = Wo[(size_t)(n0 + n) * ND + h * 64 + e];
    }
    __syncthreads();
    int n = tid & 63;
    int d0 = (tid >> 6) * 16;
    float acc[16];
    #pragma unroll
    for (int j = 0; j < 16; ++j) acc[j] = 0.f;
    for (int e = 0; e < 64; ++e) {
        float w = swo[n][e];
        #pragma unroll
        for (int j = 0; j < 16; ++j)
            acc[j] += w * skv[d0 + j][e];
    }
    size_t base = (size_t)b * ND * KK + (size_t)(n0 + n) * KK + h * 64 + d0;
    uint32_t pk[8];
    #pragma unroll
    for (int j = 0; j < 8; ++j) pk[j] = pack_f16(acc[2*j], acc[2*j+1]);
    *(uint4*)(&B2o[base])     = *(uint4*)(pk);
    *(uint4*)(&B2o[base + 8]) = *(uint4*)(pk + 4);
}

// ---------------- launch ----------------
extern "C" void kernel_launch(void* const* d_in, const int* in_sizes, int n_in,
                              void* d_out, int out_size)
{
    const float* q  = (const float*)d_in[0];
    const float* kv = (const float*)d_in[1];
    const float* Wq = (const float*)d_in[2];
    const float* bq = (const float*)d_in[3];
    const float* Wk = (const float*)d_in[4];
    const float* bk = (const float*)d_in[5];
    const float* Wv = (const float*)d_in[6];
    const float* bv = (const float*)d_in[7];
    const float* Wo = (const float*)d_in[8];
    const float* bo = (const float*)d_in[9];
    float* out = (float*)d_out;

    unsigned short *Aq, *Akv, *Azq, *Bq, *Bk, *Bv, *B2o, *feat;
    float *kvp, *ksp, *kvs, *kss;
    cudaGetSymbolAddress((void**)&Aq,   g_Aq);
    cudaGetSymbolAddress((void**)&Akv,  g_Akv);
    cudaGetSymbolAddress((void**)&Azq,  g_Azq);
    cudaGetSymbolAddress((void**)&Bq,   g_Bq);
    cudaGetSymbolAddress((void**)&Bk,   g_Bk);
    cudaGetSymbolAddress((void**)&Bv,   g_Bv);
    cudaGetSymbolAddress((void**)&B2o,  g_B2o);
    cudaGetSymbolAddress((void**)&feat, g_feat);
    cudaGetSymbolAddress((void**)&kvp,  g_kvpart);
    cudaGetSymbolAddress((void**)&ksp,  g_kspart);
    cudaGetSymbolAddress((void**)&kvs,  g_kvsum);
    cudaGetSymbolAddress((void**)&kss,  g_ksum);

    unsigned short* fk = feat + 0*(size_t)NBH*NT*NE;
    unsigned short* fv = feat + 1*(size_t)NBH*NT*NE;

    cudaFuncSetAttribute((const void*)gemm_kv,     cudaFuncAttributeMaxDynamicSharedMemorySize, GEMM_SMEM);
    cudaFuncSetAttribute((const void*)gemm_qfused, cudaFuncAttributeMaxDynamicSharedMemorySize, GEMM_SMEM);
    cudaFuncSetAttribute((const void*)gemm_o,      cudaFuncAttributeMaxDynamicSharedMemorySize, GEMM_SMEM);

    // [0] activation converts (q and kv -> fp16)
    {
        int n4 = NM*ND/4;
        int blk = (n4 + 255) / 256;
        split_pair<<<dim3(blk, 2), 256>>>((const float4*)q, (const float4*)kv, Aq, Akv);
    }
    // [1] weight prep (Wq, Wk, Wv -> fp16 [n][k])
    {
        int blk2 = (ND*ND + 255) / 256;
        wprep3<<<dim3(blk2, 3), 256>>>(Wq, Wk, Wv, Bq, Bk, Bv);
    }
    // [2] K | V projection GEMMs -> fp16 feat
    {
        dim3 grid(ND / BN, NM / BM, 2);
        gemm_kv<<<grid, 256, GEMM_SMEM>>>(Akv, Bk, Bv, bk, bv, fk, fv);
    }
    // [3][4] kv_sum / k_sum
    {
        dim3 grid(NBH, SPLITR);
        kvsum_partial<<<grid, 256>>>(fk, fv, kvp, ksp);
        kvsum_reduce<<<NBH, 256>>>(kvp, ksp, kvs, kss);
    }
    // [5] B'' = blockstack(kvsum_h * Wo_h^T) fp16, per batch
    {
        dim3 grid(ND / 64, NBH);
        buildB<<<grid, 256>>>(Wo, kvs, B2o);
    }
    // [6] Q projection fused with z-scale -> A''
    {
        dim3 grid(ND / BN, NM / BM);
        gemm_qfused<<<grid, 256, GEMM_SMEM>>>(Aq, Bq, bq, kss, Azq);
    }
    // [7] output GEMM
    {
        dim3 grid(ND / BN, NM / BM);
        gemm_o<<<grid, 256, GEMM_SMEM>>>(Azq, B2o, bo, out);
    }
}

// round 10
// speedup vs baseline: 4.0627x; 1.1356x over previous
#include <cuda_runtime.h>
#include <cuda_bf16.h>
#include <cuda_fp16.h>
#include <cstdint>
#include <cstddef>

// ---------------- problem constants ----------------
#define NB 4
#define NT 4096
#define ND 1024
#define NH 16
#define NE 64
#define NBH (NB*NH)     // 64
#define NM (NB*NT)      // 16384
#define KK 1024         // plain fp16 K (all GEMMs)
#define SPLITR 8
#define TCH (NT/SPLITR) // 512

// ---------------- GEMM tiling ----------------
#define BM 128
#define BN 128
#define TILE_BYTES (BM*128)         // 16384
#define STAGE_BYTES (2*TILE_BYTES)  // 32768
#define STAGES 3
#define GEMM_SMEM (STAGES*STAGE_BYTES)  // 98304
#define NCH (KK/64)                 // 16
#define OSCL 65536.0f
#define IOSCL (1.0f/65536.0f)

// ---------------- scratch (device globals) ----------------
__device__ unsigned short g_Aq[(size_t)NM*KK];    // q fp16
__device__ unsigned short g_Akv[(size_t)NM*KK];   // kv fp16
__device__ unsigned short g_Azq[(size_t)NM*KK];   // A'' = 2^16*z*qh2 fp16
__device__ unsigned short g_Bq[(size_t)ND*KK];    // Wq fp16 [n][k]
__device__ unsigned short g_Bk[(size_t)ND*KK];    // Wk fp16 [n][k]
__device__ unsigned short g_Bv[(size_t)ND*KK];    // Wv fp16 [n][k]
__device__ unsigned short g_B2o[(size_t)NB*ND*KK];// B'' per batch fp16 [n][k]
__device__ unsigned short g_feat[2][(size_t)NBH*NT*NE]; // kh2, vh fp16 [b,h,t,e]
__device__ float g_kvpart[(size_t)NBH*SPLITR*NE*NE];
__device__ float g_kspart[(size_t)NBH*SPLITR*NE];
__device__ float g_kvsum[(size_t)NBH*NE*NE];
__device__ float g_ksum[(size_t)NBH*NE];

// ---------------- helpers ----------------
__device__ __forceinline__ uint32_t s2u(const void* p) {
    uint32_t a;
    asm("{ .reg .u64 t; cvta.to.shared.u64 t, %1; cvt.u32.u64 %0, t; }" : "=r"(a) : "l"(p));
    return a;
}
__device__ __forceinline__ uint32_t swz(uint32_t b) { return b ^ ((b >> 3) & 0x70); }

__device__ __forceinline__ void cpasync16(uint32_t dst, const void* src) {
    asm volatile("cp.async.cg.shared.global [%0], [%1], 16;" :: "r"(dst), "l"(src));
}
__device__ __forceinline__ void cp_commit() {
    asm volatile("cp.async.commit_group;" ::: "memory");
}
template<int N>
__device__ __forceinline__ void cp_wait() {
    asm volatile("cp.async.wait_group %0;" :: "n"(N) : "memory");
}
__device__ __forceinline__ void ldsm4(uint32_t* r, uint32_t addr) {
    asm volatile("ldmatrix.sync.aligned.m8n8.x4.shared.b16 {%0,%1,%2,%3}, [%4];"
                 : "=r"(r[0]), "=r"(r[1]), "=r"(r[2]), "=r"(r[3]) : "r"(addr));
}
__device__ __forceinline__ void ldsm4t(uint32_t* r, uint32_t addr) {
    asm volatile("ldmatrix.sync.aligned.m8n8.x4.trans.shared.b16 {%0,%1,%2,%3}, [%4];"
                 : "=r"(r[0]), "=r"(r[1]), "=r"(r[2]), "=r"(r[3]) : "r"(addr));
}
__device__ __forceinline__ void mma_fp16(float* c, const uint32_t* a, const uint32_t* b) {
    asm volatile(
        "mma.sync.aligned.m16n8k16.row.col.f32.f16.f16.f32 "
        "{%0,%1,%2,%3}, {%4,%5,%6,%7}, {%8,%9}, {%0,%1,%2,%3};"
        : "+f"(c[0]), "+f"(c[1]), "+f"(c[2]), "+f"(c[3])
        : "r"(a[0]), "r"(a[1]), "r"(a[2]), "r"(a[3]), "r"(b[0]), "r"(b[1]));
}
__device__ __forceinline__ uint32_t pack_f16(float a, float b) {   // ushort2(h(a), h(b))
    uint32_t r;
    asm("cvt.rn.f16x2.f32 %0, %1, %2;" : "=r"(r) : "f"(b), "f"(a));
    return r;
}

// ---------------- prep kernels ----------------
// fp32 -> fp16 convert; grid.y selects (q -> Aq) / (kv -> Akv)
__global__ void split_pair(const float4* __restrict__ xq, const float4* __restrict__ xkv,
                           unsigned short* __restrict__ Aq, unsigned short* __restrict__ Akv) {
    int gi = blockIdx.x * blockDim.x + threadIdx.x;
    if (gi >= NM*ND/4) return;
    const float4* x = (blockIdx.y == 0) ? xq : xkv;
    unsigned short* A = (blockIdx.y == 0) ? Aq : Akv;
    float4 v = x[gi];
    uint32_t p01 = pack_f16(v.x, v.y);
    uint32_t p23 = pack_f16(v.z, v.w);
    *(uint2*)(A + (size_t)gi * 4) = make_uint2(p01, p23);
}
// weight prep: y in {0,1,2} -> Wq,Wk,Wv as fp16 [n][k], n=h*64+e
__global__ void wprep3(const float* __restrict__ Wq, const float* __restrict__ Wk,
                       const float* __restrict__ Wv,
                       unsigned short* __restrict__ Bq, unsigned short* __restrict__ Bk,
                       unsigned short* __restrict__ Bv) {
    int idx = blockIdx.x * blockDim.x + threadIdx.x;
    if (idx >= ND*ND) return;
    int which = blockIdx.y;
    int n = idx >> 10, k = idx & 1023;
    const float* W = (which == 0) ? Wq : (which == 1) ? Wk : Wv;
    float v = W[((size_t)(n >> 6) * ND + k) * NE + (n & 63)];
    unsigned short h = __half_as_ushort(__float2half_rn(v));
    (((which == 0) ? Bq : (which == 1) ? Bk : Bv))[idx] = h;
}

// ---------------- shared fp16 GEMM mainloop (K fixed = KK) ----------------
__device__ __forceinline__ void gemm_mainloop(
    uint32_t sb, const unsigned short* __restrict__ A, const unsigned short* __restrict__ Bm,
    int m0, int n0, int tid, int lane, int wid, float acc[4][4][4])
{
    const int lrow = tid >> 3, lkc = tid & 7;
    const int mw = (wid >> 2) * 64, nw = (wid & 3) * 32;
    const int arow = mw + (lane & 15);
    const int brow = nw + (lane & 7) + ((lane >> 4) & 1) * 8;

    #pragma unroll
    for (int s = 0; s < STAGES - 1; ++s) {
        uint32_t sA = sb + s * STAGE_BYTES, sB = sA + TILE_BYTES;
        int k0 = s * 64;
        #pragma unroll
        for (int i = 0; i < 4; ++i) {
            int row = lrow + i * 32;
            uint32_t so = swz(row * 128 + lkc * 16);
            cpasync16(sA + so, A  + (size_t)(m0 + row) * KK + k0 + lkc * 8);
            cpasync16(sB + so, Bm + (size_t)(n0 + row) * KK + k0 + lkc * 8);
        }
        cp_commit();
    }
    for (int ch = 0; ch < NCH; ++ch) {
        cp_wait<STAGES - 2>();
        __syncthreads();
        int chn = ch + STAGES - 1;
        if (chn < NCH) {
            int sl = chn % STAGES;
            uint32_t sA = sb + sl * STAGE_BYTES, sB = sA + TILE_BYTES;
            int k0 = chn * 64;
            #pragma unroll
            for (int i = 0; i < 4; ++i) {
                int row = lrow + i * 32;
                uint32_t so = swz(row * 128 + lkc * 16);
                cpasync16(sA + so, A  + (size_t)(m0 + row) * KK + k0 + lkc * 8);
                cpasync16(sB + so, Bm + (size_t)(n0 + row) * KK + k0 + lkc * 8);
            }
        }
        cp_commit();
        const int s = ch % STAGES;
        const uint32_t aBase = sb + s * STAGE_BYTES;
        const uint32_t bBase = aBase + TILE_BYTES;
        #pragma unroll
        for (int k16 = 0; k16 < 4; ++k16) {
            uint32_t a[4][4], bf[2][4];
            const int acol = (k16 * 16 + (lane >> 4) * 8) * 2;
            const int bcol = (k16 * 16 + ((lane >> 3) & 1) * 8) * 2;
            #pragma unroll
            for (int mi = 0; mi < 4; ++mi)
                ldsm4(a[mi], aBase + swz((arow + mi * 16) * 128 + acol));
            #pragma unroll
            for (int nj = 0; nj < 2; ++nj)
                ldsm4(bf[nj], bBase + swz((brow + nj * 16) * 128 + bcol));
            #pragma unroll
            for (int mi = 0; mi < 4; ++mi)
                #pragma unroll
                for (int n8 = 0; n8 < 4; ++n8)
                    mma_fp16(acc[mi][n8], a[mi], &bf[n8 >> 1][(n8 & 1) * 2]);
        }
    }
}

// ---------------- K|V projection GEMM (blockIdx.z: 0=K squared, 1=V) --------
// outputs fp16 feat [b,h,t,e]
__global__ void __launch_bounds__(256, 2) gemm_kv(
    const unsigned short* __restrict__ Akv,
    const unsigned short* __restrict__ Bk, const unsigned short* __restrict__ Bv,
    const float* __restrict__ bk, const float* __restrict__ bv,
    unsigned short* __restrict__ fk, unsigned short* __restrict__ fv)
{
    extern __shared__ __align__(128) char smem[];
    const uint32_t sb = s2u(smem);
    const int tid = threadIdx.x, lane = tid & 31, wid = tid >> 5;
    const int m0 = blockIdx.y * BM, n0 = blockIdx.x * BN;
    const int which = blockIdx.z;
    const unsigned short* Bm = (which == 0) ? Bk : Bv;
    const float* bias = (which == 0) ? bk : bv;
    unsigned short* C = (which == 0) ? fk : fv;

    float acc[4][4][4];
    #pragma unroll
    for (int i = 0; i < 4; ++i)
        #pragma unroll
        for (int j = 0; j < 4; ++j)
            #pragma unroll
            for (int r = 0; r < 4; ++r) acc[i][j][r] = 0.f;

    gemm_mainloop(sb, Akv, Bm, m0, n0, tid, lane, wid, acc);

    const int g = lane >> 2, t2 = (lane & 3) * 2;
    const int mw = (wid >> 2) * 64, nw = (wid & 3) * 32;
    #pragma unroll
    for (int mi = 0; mi < 4; ++mi) {
        #pragma unroll
        for (int n8 = 0; n8 < 4; ++n8) {
            int col = n0 + nw + n8 * 8 + t2;
            float b0 = bias[col], b1 = bias[col + 1];
            int r0 = m0 + mw + mi * 16 + g;
            int r1 = r0 + 8;
            float v00 = acc[mi][n8][0] + b0, v01 = acc[mi][n8][1] + b1;
            float v10 = acc[mi][n8][2] + b0, v11 = acc[mi][n8][3] + b1;
            if (which == 0) { v00 *= v00; v01 *= v01; v10 *= v10; v11 *= v11; }
            int h = col >> 6, e = col & 63;
            int b_0 = r0 >> 12, t_0 = r0 & (NT - 1);
            int b_1 = r1 >> 12, t_1 = r1 & (NT - 1);
            *(uint32_t*)(C + ((((size_t)b_0 * NH + h) * NT + t_0) * NE + e)) = pack_f16(v00, v01);
            *(uint32_t*)(C + ((((size_t)b_1 * NH + h) * NT + t_1) * NE + e)) = pack_f16(v10, v11);
        }
    }
}

// ---------------- Q projection GEMM fused with z-scale -> A'' ---------------
__global__ void __launch_bounds__(256, 2) gemm_qfused(
    const unsigned short* __restrict__ Aq, const unsigned short* __restrict__ Bq,
    const float* __restrict__ bq, const float* __restrict__ kss,
    unsigned short* __restrict__ Azq)
{
    extern __shared__ __align__(128) char smem[];
    const uint32_t sb = s2u(smem);
    const int tid = threadIdx.x, lane = tid & 31, wid = tid >> 5;
    const int m0 = blockIdx.y * BM, n0 = blockIdx.x * BN;

    float acc[4][4][4];
    #pragma unroll
    for (int i = 0; i < 4; ++i)
        #pragma unroll
        for (int j = 0; j < 4; ++j)
            #pragma unroll
            for (int r = 0; r < 4; ++r) acc[i][j][r] = 0.f;

    gemm_mainloop(sb, Aq, Bq, m0, n0, tid, lane, wid, acc);

    const int g = lane >> 2, t2 = (lane & 3) * 2;
    const int mw = (wid >> 2) * 64, nw = (wid & 3) * 32;
    const int b = m0 >> 12;
    const int hloc = nw >> 6;                 // 0 or 1
    const int h = (n0 >> 6) + hloc;           // global head
    const int bh = b * NH + h;

    float ks0[4], ks1[4];
    #pragma unroll
    for (int n8 = 0; n8 < 4; ++n8) {
        int colh = (nw & 32) + n8 * 8 + t2;
        ks0[n8] = kss[bh * NE + colh];
        ks1[n8] = kss[bh * NE + colh + 1];
    }

    float* zred = (float*)smem;               // 256 floats: [t_local][head_local]
    __syncthreads();
    if (tid < 256) zred[tid] = 0.f;
    __syncthreads();

    float part[4][2];
    #pragma unroll
    for (int mi = 0; mi < 4; ++mi) { part[mi][0] = 0.f; part[mi][1] = 0.f; }
    #pragma unroll
    for (int mi = 0; mi < 4; ++mi) {
        #pragma unroll
        for (int n8 = 0; n8 < 4; ++n8) {
            int col = n0 + nw + n8 * 8 + t2;
            float b0 = bq[col], b1 = bq[col + 1];
            float q00 = acc[mi][n8][0] + b0; q00 *= q00;
            float q01 = acc[mi][n8][1] + b1; q01 *= q01;
            float q10 = acc[mi][n8][2] + b0; q10 *= q10;
            float q11 = acc[mi][n8][3] + b1; q11 *= q11;
            acc[mi][n8][0] = q00; acc[mi][n8][1] = q01;
            acc[mi][n8][2] = q10; acc[mi][n8][3] = q11;
            part[mi][0] += q00 * ks0[n8] + q01 * ks1[n8];
            part[mi][1] += q10 * ks0[n8] + q11 * ks1[n8];
        }
    }
    #pragma unroll
    for (int mi = 0; mi < 4; ++mi) {
        int tl0 = mw + mi * 16 + g;
        atomicAdd(&zred[tl0 * 2 + hloc], part[mi][0]);
        atomicAdd(&zred[(tl0 + 8) * 2 + hloc], part[mi][1]);
    }
    __syncthreads();

    #pragma unroll
    for (int mi = 0; mi < 4; ++mi) {
        int tl0 = mw + mi * 16 + g;
        float z0 = OSCL / (zred[tl0 * 2 + hloc] + 1e-6f);
        float z1 = OSCL / (zred[(tl0 + 8) * 2 + hloc] + 1e-6f);
        int r0 = m0 + tl0;
        #pragma unroll
        for (int n8 = 0; n8 < 4; ++n8) {
            int colh = (nw & 32) + n8 * 8 + t2;
            *(uint32_t*)(Azq + (size_t)r0 * KK + h * NE + colh) =
                pack_f16(acc[mi][n8][0] * z0, acc[mi][n8][1] * z0);
            *(uint32_t*)(Azq + (size_t)(r0 + 8) * KK + h * NE + colh) =
                pack_f16(acc[mi][n8][2] * z1, acc[mi][n8][3] * z1);
        }
    }
}

// ---------------- O GEMM: out = (A'' x B''_b)*2^-16 + bo ----------------
__global__ void __launch_bounds__(256, 2) gemm_o(
    const unsigned short* __restrict__ A2, const unsigned short* __restrict__ B2o,
    const float* __restrict__ bo, float* __restrict__ out)
{
    extern __shared__ __align__(128) char smem[];
    const uint32_t sb = s2u(smem);
    const int tid = threadIdx.x, lane = tid & 31, wid = tid >> 5;
    const int m0 = blockIdx.y * BM, n0 = blockIdx.x * BN;
    const unsigned short* Bm = B2o + (size_t)(m0 >> 12) * ND * KK;

    float acc[4][4][4];
    #pragma unroll
    for (int i = 0; i < 4; ++i)
        #pragma unroll
        for (int j = 0; j < 4; ++j)
            #pragma unroll
            for (int r = 0; r < 4; ++r) acc[i][j][r] = 0.f;

    gemm_mainloop(sb, A2, Bm, m0, n0, tid, lane, wid, acc);

    const int g = lane >> 2, t2 = (lane & 3) * 2;
    const int mw = (wid >> 2) * 64, nw = (wid & 3) * 32;
    #pragma unroll
    for (int mi = 0; mi < 4; ++mi) {
        #pragma unroll
        for (int n8 = 0; n8 < 4; ++n8) {
            int col = n0 + nw + n8 * 8 + t2;
            float b0 = bo[col], b1 = bo[col + 1];
            int r0 = m0 + mw + mi * 16 + g;
            int r1 = r0 + 8;
            float2 v0 = make_float2(acc[mi][n8][0] * IOSCL + b0, acc[mi][n8][1] * IOSCL + b1);
            float2 v1 = make_float2(acc[mi][n8][2] * IOSCL + b0, acc[mi][n8][3] * IOSCL + b1);
            *(float2*)(out + (size_t)r0 * ND + col) = v0;
            *(float2*)(out + (size_t)r1 * ND + col) = v1;
        }
    }
}

// ---------------- kv_sum & k_sum via tensor cores (ldmatrix.trans) ----------
// Per (bh, split): C[64d][64e] = sum_t kh2[t][d] * vh[t][e], K = t (512)
// ksum via extra MMA with constant all-ones B fragment.
__global__ void __launch_bounds__(128) kvsum_mma(
    const unsigned short* __restrict__ kh2, const unsigned short* __restrict__ vh,
    float* __restrict__ kvp, float* __restrict__ ksp)
{
    __shared__ __align__(128) unsigned char sm[2 * 16384];  // 2 stages x (8KB k + 8KB v)
    const uint32_t sb = s2u(sm);
    const int bh = blockIdx.x, sp = blockIdx.y;
    const unsigned short* kb = kh2 + ((size_t)bh * NT + (size_t)sp * TCH) * NE;
    const unsigned short* vb = vh  + ((size_t)bh * NT + (size_t)sp * TCH) * NE;
    const int tid = threadIdx.x, lane = tid & 31, wid = tid >> 5;
    const int dbase = wid * 16;

    float c[8][4];
    #pragma unroll
    for (int i = 0; i < 8; ++i)
        #pragma unroll
        for (int r = 0; r < 4; ++r) c[i][r] = 0.f;
    float co[4] = {0.f, 0.f, 0.f, 0.f};
    const uint32_t onesr[2] = {0x3C003C00u, 0x3C003C00u};

    // ldsm.trans lane pointers (within a 16k x 16 tile):
    const int akrow = (lane & 7) + ((lane >> 4) & 1) * 8;     // A: bit4 -> k-block
    const int adcol = dbase + ((lane >> 3) & 1) * 8;          //    bit3 -> d-block
    const int bkrow = (lane & 7) + ((lane >> 3) & 1) * 8;     // B: bit3 -> k-block
    const int bnadd = ((lane >> 4) & 1) * 8;                  //    bit4 -> n-block

    // stage fill: 64 t-rows x 128B per array; 512 16B segs per array
    #define KV_FILL(stage, t0) do {                                            \
        uint32_t base_ = sb + (stage) * 16384;                                  \
        _Pragma("unroll")                                                       \
        for (int j_ = 0; j_ < 4; ++j_) {                                        \
            int idx_ = tid + j_ * 128;                                          \
            int row_ = idx_ >> 3, seg_ = idx_ & 7;                              \
            uint32_t so_ = swz(row_ * 128 + seg_ * 16);                         \
            cpasync16(base_ + so_,        kb + (size_t)((t0) + row_) * NE + seg_ * 8); \
            cpasync16(base_ + 8192 + so_, vb + (size_t)((t0) + row_) * NE + seg_ * 8); \
        }                                                                        \
        cp_commit();                                                            \
    } while (0)

    KV_FILL(0, 0);
    #pragma unroll
    for (int ch = 0; ch < TCH / 64; ++ch) {
        cp_wait<0>();
        __syncthreads();
        if (ch + 1 < TCH / 64) KV_FILL((ch + 1) & 1, (ch + 1) * 64);
        uint32_t kbase = sb + (ch & 1) * 16384;
        uint32_t vbase = kbase + 8192;
        #pragma unroll
        for (int k16 = 0; k16 < 4; ++k16) {
            int kl = k16 * 16;
            uint32_t a[4];
            ldsm4t(a, kbase + swz((kl + akrow) * 128 + adcol * 2));
            #pragma unroll
            for (int nb = 0; nb < 4; ++nb) {
                uint32_t bf[4];
                ldsm4t(bf, vbase + swz((kl + bkrow) * 128 + (nb * 16 + bnadd) * 2));
                mma_fp16(c[nb * 2],     a, bf);
                mma_fp16(c[nb * 2 + 1], a, bf + 2);
            }
            mma_fp16(co, a, onesr);
        }
        __syncthreads();
    }
    #undef KV_FILL

    const int g = lane >> 2, t2 = (lane & 3) * 2;
    float* outp = kvp + ((size_t)(bh * SPLITR + sp)) * NE * NE;
    #pragma unroll
    for (int nb2 = 0; nb2 < 8; ++nb2) {
        int ebase = (nb2 >> 1) * 16 + (nb2 & 1) * 8;
        *(float2*)&outp[(size_t)(dbase + g) * NE + ebase + t2] =
            make_float2(c[nb2][0], c[nb2][1]);
        *(float2*)&outp[(size_t)(dbase + g + 8) * NE + ebase + t2] =
            make_float2(c[nb2][2], c[nb2][3]);
    }
    if ((lane & 3) == 0) {
        float* kso = ksp + (size_t)(bh * SPLITR + sp) * NE;
        kso[dbase + g]     = co[0];
        kso[dbase + g + 8] = co[2];
    }
}

__global__ void kvsum_reduce(const float* __restrict__ kvp, const float* __restrict__ ksp,
                             float* __restrict__ kvs, float* __restrict__ kss)
{
    int bh = blockIdx.x;
    int tid = threadIdx.x;
    for (int i = tid; i < NE*NE; i += 256) {
        float s = 0.f;
        #pragma unroll
        for (int sp = 0; sp < SPLITR; ++sp)
            s += kvp[((size_t)(bh*SPLITR + sp))*NE*NE + i];
        kvs[(size_t)bh*NE*NE + i] = s;
    }
    if (tid < NE) {
        float s = 0.f;
        #pragma unroll
        for (int sp = 0; sp < SPLITR; ++sp)
            s += ksp[(size_t)(bh*SPLITR + sp)*NE + tid];
        kss[(size_t)bh*NE + tid] = s;
    }
}

// ---------------- B'' build: B''_b[n][h*64+d] = sum_e kvsum[b,h][d][e]*Wo[n][h*64+e]
__global__ __launch_bounds__(256) void buildB(
    const float* __restrict__ Wo, const float* __restrict__ kvs,
    unsigned short* __restrict__ B2o)
{
    int bh = blockIdx.y;
    int b = bh >> 4, h = bh & 15;
    int n0 = blockIdx.x * 64;
    __shared__ float skv[64][64];
    __shared__ float swo[64][65];
    int tid = threadIdx.x;
    for (int i = tid; i < 4096; i += 256)
        ((float*)skv)[i] = kvs[(size_t)bh*4096 + i];
    for (int i = tid; i < 4096; i += 256) {
        int n = i >> 6, e = i & 63;
        swo[n][e] = Wo[(size_t)(n0 + n) * ND + h * 64 + e];
    }
    __syncthreads();
    int n = tid & 63;
    int d0 = (tid >> 6) * 16;
    float acc[16];
    #pragma unroll
    for (int j = 0; j < 16; ++j) acc[j] = 0.f;
    for (int e = 0; e < 64; ++e) {
        float w = swo[n][e];
        #pragma unroll
        for (int j = 0; j < 16; ++j)
            acc[j] += w * skv[d0 + j][e];
    }
    size_t base = (size_t)b * ND * KK + (size_t)(n0 + n) * KK + h * 64 + d0;
    uint32_t pk[8];
    #pragma unroll
    for (int j = 0; j < 8; ++j) pk[j] = pack_f16(acc[2*j], acc[2*j+1]);
    *(uint4*)(&B2o[base])     = *(uint4*)(pk);
    *(uint4*)(&B2o[base + 8]) = *(uint4*)(pk + 4);
}

// ---------------- launch ----------------
extern "C" void kernel_launch(void* const* d_in, const int* in_sizes, int n_in,
                              void* d_out, int out_size)
{
    const float* q  = (const float*)d_in[0];
    const float* kv = (const float*)d_in[1];
    const float* Wq = (const float*)d_in[2];
    const float* bq = (const float*)d_in[3];
    const float* Wk = (const float*)d_in[4];
    const float* bk = (const float*)d_in[5];
    const float* Wv = (const float*)d_in[6];
    const float* bv = (const float*)d_in[7];
    const float* Wo = (const float*)d_in[8];
    const float* bo = (const float*)d_in[9];
    float* out = (float*)d_out;

    unsigned short *Aq, *Akv, *Azq, *Bq, *Bk, *Bv, *B2o, *feat;
    float *kvp, *ksp, *kvs, *kss;
    cudaGetSymbolAddress((void**)&Aq,   g_Aq);
    cudaGetSymbolAddress((void**)&Akv,  g_Akv);
    cudaGetSymbolAddress((void**)&Azq,  g_Azq);
    cudaGetSymbolAddress((void**)&Bq,   g_Bq);
    cudaGetSymbolAddress((void**)&Bk,   g_Bk);
    cudaGetSymbolAddress((void**)&Bv,   g_Bv);
    cudaGetSymbolAddress((void**)&B2o,  g_B2o);
    cudaGetSymbolAddress((void**)&feat, g_feat);
    cudaGetSymbolAddress((void**)&kvp,  g_kvpart);
    cudaGetSymbolAddress((void**)&ksp,  g_kspart);
    cudaGetSymbolAddress((void**)&kvs,  g_kvsum);
    cudaGetSymbolAddress((void**)&kss,  g_ksum);

    unsigned short* fk = feat + 0*(size_t)NBH*NT*NE;
    unsigned short* fv = feat + 1*(size_t)NBH*NT*NE;

    cudaFuncSetAttribute((const void*)gemm_kv,     cudaFuncAttributeMaxDynamicSharedMemorySize, GEMM_SMEM);
    cudaFuncSetAttribute((const void*)gemm_qfused, cudaFuncAttributeMaxDynamicSharedMemorySize, GEMM_SMEM);
    cudaFuncSetAttribute((const void*)gemm_o,      cudaFuncAttributeMaxDynamicSharedMemorySize, GEMM_SMEM);

    // [0] activation converts (q and kv -> fp16)
    {
        int n4 = NM*ND/4;
        int blk = (n4 + 255) / 256;
        split_pair<<<dim3(blk, 2), 256>>>((const float4*)q, (const float4*)kv, Aq, Akv);
    }
    // [1] weight prep (Wq, Wk, Wv -> fp16 [n][k])
    {
        int blk2 = (ND*ND + 255) / 256;
        wprep3<<<dim3(blk2, 3), 256>>>(Wq, Wk, Wv, Bq, Bk, Bv);
    }
    // [2] K | V projection GEMMs -> fp16 feat
    {
        dim3 grid(ND / BN, NM / BM, 2);
        gemm_kv<<<grid, 256, GEMM_SMEM>>>(Akv, Bk, Bv, bk, bv, fk, fv);
    }
    // [3][4] kv_sum / k_sum (tensor-core MMA)
    {
        dim3 grid(NBH, SPLITR);
        kvsum_mma<<<grid, 128>>>(fk, fv, kvp, ksp);
        kvsum_reduce<<<NBH, 256>>>(kvp, ksp, kvs, kss);
    }
    // [5] B'' = blockstack(kvsum_h * Wo_h^T) fp16, per batch
    {
        dim3 grid(ND / 64, NBH);
        buildB<<<grid, 256>>>(Wo, kvs, B2o);
    }
    // [6] Q projection fused with z-scale -> A''
    {
        dim3 grid(ND / BN, NM / BM);
        gemm_qfused<<<grid, 256, GEMM_SMEM>>>(Aq, Bq, bq, kss, Azq);
    }
    // [7] output GEMM
    {
        dim3 grid(ND / BN, NM / BM);
        gemm_o<<<grid, 256, GEMM_SMEM>>>(Azq, B2o, bo, out);
    }
}